// round 11
// baseline (speedup 1.0000x reference)
#include <cuda_runtime.h>
#include <cuda_fp16.h>
#include <cuda_bf16.h>

#define NN 50000
#define NE 800000
#define HD 128
#define NMAT 14
#define NSB 49   // scan blocks: ceil(50000/1024)

// ---------------- device scratch (no allocations allowed) ----------------
__device__ __half  g_yh[(size_t)NN * HD];   // fp16 messages (GEMM output, norm-scaled)
__device__ __half  g_hh[(size_t)NN * HD];   // fp16 block intermediate h
__device__ __half  g_xh[(size_t)NN * HD];   // fp16 running x master
__device__ float   g_norm[NN];
__device__ int     g_rowptr[NN + 1];
__device__ int     g_cnt[NN];
__device__ int     g_off[NN];
__device__ int     g_col[NE];
__device__ int     g_bsum[NSB];             // raw per-block totals
__device__ __half  g_wh[(size_t)NMAT * HD * HD];  // weights, n-major, fp16 hi
__device__ __half  g_wl[(size_t)NMAT * HD * HD];  // fp16 lo residual

__device__ __forceinline__ float lk(float v) { return v >= 0.f ? v : 0.01f * v; }

__device__ __forceinline__ float2 u2f2(unsigned u) {
    __half2 h = *reinterpret_cast<__half2*>(&u);
    return __half22float2(h);
}

// ---------------- CSR build ----------------
__global__ void count_kernel(const int* __restrict__ dst) {
    int e = blockIdx.x * blockDim.x + threadIdx.x;
    if (e < NE) atomicAdd(&g_cnt[dst[e]], 1);
}

__global__ __launch_bounds__(1024) void scan_blocks_kernel() {
    __shared__ int ws[32];
    int tid = threadIdx.x, lane = tid & 31, wid = tid >> 5;
    int i = blockIdx.x * 1024 + tid;
    int v = (i < NN) ? g_cnt[i] : 0;
    int x = v;
#pragma unroll
    for (int d = 1; d < 32; d <<= 1) {
        int t = __shfl_up_sync(0xffffffffu, x, d);
        if (lane >= d) x += t;
    }
    if (lane == 31) ws[wid] = x;
    __syncthreads();
    if (wid == 0) {
        int s = ws[lane];
#pragma unroll
        for (int d = 1; d < 32; d <<= 1) {
            int t = __shfl_up_sync(0xffffffffu, s, d);
            if (lane >= d) s += t;
        }
        ws[lane] = s;
    }
    __syncthreads();
    int off = wid ? ws[wid - 1] : 0;
    if (i < NN) g_rowptr[i] = off + x - v;
    if (tid == 1023) g_bsum[blockIdx.x] = off + x;
}

__global__ __launch_bounds__(1024) void scan_fix_kernel() {
    __shared__ int s_off;
    int tid = threadIdx.x;
    if (tid < 32) {
        int b = blockIdx.x;
        int t0 = (tid < NSB && tid < b) ? g_bsum[tid] : 0;
        int t1 = (tid + 32 < NSB && tid + 32 < b) ? g_bsum[tid + 32] : 0;
        int s = t0 + t1;
#pragma unroll
        for (int d = 16; d >= 1; d >>= 1) s += __shfl_xor_sync(0xffffffffu, s, d);
        if (tid == 0) s_off = s;
    }
    __syncthreads();
    int i = blockIdx.x * 1024 + tid;
    if (i < NN) {
        int r = g_rowptr[i] + s_off;
        g_rowptr[i] = r;
        g_off[i] = r;
        g_norm[i] = rsqrtf(1.0f + (float)g_cnt[i]);
    }
    if (blockIdx.x == 0 && tid == 0) g_rowptr[NN] = NE;
}

__global__ void fill_kernel(const int* __restrict__ src, const int* __restrict__ dst) {
    int e = blockIdx.x * blockDim.x + threadIdx.x;
    if (e < NE) {
        int d = dst[e];
        int p = atomicAdd(&g_off[d], 1);
        g_col[p] = src[e];
    }
}

// ---------------- weight prep: transpose to n-major, split fp32 -> fp16 hi/lo ----
__global__ void prep_w_kernel(const float* __restrict__ w_in, const float* __restrict__ w1,
                              const float* __restrict__ w2, const float* __restrict__ w_out) {
    int idx = blockIdx.x * blockDim.x + threadIdx.x;
    if (idx >= NMAT * HD * HD) return;
    int mat = idx >> 14;
    int rem = idx & 16383;
    int n = rem >> 7, k = rem & 127;
    float v;
    if (mat == 0)       v = w_in[k * HD + n];
    else if (mat <= 6)  v = w1[(size_t)(mat - 1) * HD * HD + k * HD + n];
    else if (mat <= 12) v = w2[(size_t)(mat - 7) * HD * HD + k * HD + n];
    else                v = (n < 64) ? w_out[k * 64 + n] : 0.f;
    __half hi = __float2half_rn(v);
    __half lo = __float2half_rn(v - __half2float(hi));
    g_wh[idx] = hi;
    g_wl[idx] = lo;
}

// ---------------- fp16 MMA helper (fp32 accumulate) ----------------
__device__ __forceinline__ void mma_f16(float* c, unsigned a0, unsigned a1, unsigned a2,
                                        unsigned a3, unsigned b0, unsigned b1) {
    asm volatile(
        "mma.sync.aligned.m16n8k16.row.col.f32.f16.f16.f32 "
        "{%0,%1,%2,%3}, {%4,%5,%6,%7}, {%8,%9}, {%0,%1,%2,%3};"
        : "+f"(c[0]), "+f"(c[1]), "+f"(c[2]), "+f"(c[3])
        : "r"(a0), "r"(a1), "r"(a2), "r"(a3), "r"(b0), "r"(b1));
}

// ---------------- single-stage tensor-core GEMM (full K resident, 1 sync) -------
// Y = half((A@W)*norm), K=128. A fp32->fp16 or fp16; W split fp16 hi/lo.
template <int BN, typename AT>
__global__ __launch_bounds__(256, 2) void gemm_tc_kernel(const AT* __restrict__ A,
                                                         const __half* __restrict__ Wh,
                                                         const __half* __restrict__ Wl,
                                                         __half* __restrict__ Yh) {
    constexpr int BM = 128, K = 128;
    constexpr int WN = BN / 4;   // 32 or 16
    constexpr int NT = WN / 8;   // 4 or 2
    constexpr int SA = 136;      // row stride in halves (128 + 8 pad)
    extern __shared__ __half smem[];
    __half* sA  = smem;              // 128 * SA
    __half* sBh = sA + BM * SA;      // BN * SA
    __half* sBl = sBh + BN * SA;     // BN * SA

    const int tid = threadIdx.x, lane = tid & 31, wid = tid >> 5;
    const int g = lane >> 2, t = lane & 3;
    const int wm = (wid & 1) * 64, wn = (wid >> 1) * WN;
    const int m0 = blockIdx.x * BM;

    // ---- bulk load: A full tile ----
    {
        int r = tid >> 1, kh = (tid & 1) * 64;
        bool ok = (m0 + r) < NN;
        if constexpr (sizeof(AT) == 4) {
            const float* Ap = (const float*)A + (size_t)(m0 + r) * K + kh;
#pragma unroll
            for (int j = 0; j < 16; j++) {
                float4 v = make_float4(0.f, 0.f, 0.f, 0.f);
                if (ok) v = *(const float4*)(Ap + j * 4);
                __half2 h01 = __floats2half2_rn(v.x, v.y);
                __half2 h23 = __floats2half2_rn(v.z, v.w);
                *(__half2*)&sA[r * SA + kh + j * 4]     = h01;
                *(__half2*)&sA[r * SA + kh + j * 4 + 2] = h23;
            }
        } else {
            const __half* Ap = (const __half*)A + (size_t)(m0 + r) * K + kh;
#pragma unroll
            for (int j = 0; j < 8; j++) {
                uint4 v = make_uint4(0u, 0u, 0u, 0u);
                if (ok) v = *(const uint4*)(Ap + j * 8);
                *(uint4*)&sA[r * SA + kh + j * 8] = v;
            }
        }
    }
    // ---- bulk load: B full tiles (hi + lo) ----
    if constexpr (BN == 128) {
        int n = tid >> 1, kh = (tid & 1) * 64;
#pragma unroll
        for (int j = 0; j < 8; j++) {
            *(uint4*)&sBh[n * SA + kh + j * 8] = *(const uint4*)&Wh[(size_t)n * K + kh + j * 8];
            *(uint4*)&sBl[n * SA + kh + j * 8] = *(const uint4*)&Wl[(size_t)n * K + kh + j * 8];
        }
    } else {
        int n = tid >> 2, kh = (tid & 3) * 32;
#pragma unroll
        for (int j = 0; j < 4; j++) {
            *(uint4*)&sBh[n * SA + kh + j * 8] = *(const uint4*)&Wh[(size_t)n * K + kh + j * 8];
            *(uint4*)&sBl[n * SA + kh + j * 8] = *(const uint4*)&Wl[(size_t)n * K + kh + j * 8];
        }
    }
    __syncthreads();

    float acc[4][NT][4];
#pragma unroll
    for (int i = 0; i < 4; i++)
#pragma unroll
        for (int j = 0; j < NT; j++)
#pragma unroll
            for (int q = 0; q < 4; q++) acc[i][j][q] = 0.f;

#pragma unroll 2
    for (int kk = 0; kk < K; kk += 16) {
        unsigned bh[NT][2], bl[NT][2];
#pragma unroll
        for (int nt = 0; nt < NT; nt++) {
            int n = wn + nt * 8 + g;
            bh[nt][0] = *(const unsigned*)&sBh[n * SA + kk + 2 * t];
            bh[nt][1] = *(const unsigned*)&sBh[n * SA + kk + 2 * t + 8];
            bl[nt][0] = *(const unsigned*)&sBl[n * SA + kk + 2 * t];
            bl[nt][1] = *(const unsigned*)&sBl[n * SA + kk + 2 * t + 8];
        }
#pragma unroll
        for (int mt = 0; mt < 4; mt++) {
            int m = wm + mt * 16 + g;
            unsigned a0 = *(const unsigned*)&sA[m * SA + kk + 2 * t];
            unsigned a1 = *(const unsigned*)&sA[(m + 8) * SA + kk + 2 * t];
            unsigned a2 = *(const unsigned*)&sA[m * SA + kk + 2 * t + 8];
            unsigned a3 = *(const unsigned*)&sA[(m + 8) * SA + kk + 2 * t + 8];
#pragma unroll
            for (int nt = 0; nt < NT; nt++) {
                mma_f16(acc[mt][nt], a0, a1, a2, a3, bh[nt][0], bh[nt][1]);
                mma_f16(acc[mt][nt], a0, a1, a2, a3, bl[nt][0], bl[nt][1]);
            }
        }
    }

#pragma unroll
    for (int mt = 0; mt < 4; mt++) {
        int r0 = m0 + wm + mt * 16 + g, r1 = r0 + 8;
        float n0 = (r0 < NN) ? g_norm[r0] : 0.f;
        float n1 = (r1 < NN) ? g_norm[r1] : 0.f;
#pragma unroll
        for (int nt = 0; nt < NT; nt++) {
            int col = wn + nt * 8 + 2 * t;
            if (r0 < NN) {
                __half2 h = __floats2half2_rn(acc[mt][nt][0] * n0, acc[mt][nt][1] * n0);
                *(__half2*)(Yh + (size_t)r0 * BN + col) = h;
            }
            if (r1 < NN) {
                __half2 h = __floats2half2_rn(acc[mt][nt][2] * n1, acc[mt][nt][3] * n1);
                *(__half2*)(Yh + (size_t)r1 * BN + col) = h;
            }
        }
    }
}

// ---------------- Aggregation (128-wide): paired-edge uint4 gather ---------------
// Warp split into 2 half-warps: one LDG.128 fetches 2 source rows.
// o = norm[n]*(y[n] + sum y[src]) + bias
// MODE 0: leaky(o) -> half buffer  MODE 1: x=(x+leaky(o))/2 in place
// MODE 3: MODE 1 + unrounded fp32 mirror to out2
#define ACC8(vv) { float2 t0_ = u2f2(vv.x), t1_ = u2f2(vv.y), t2_ = u2f2(vv.z), t3_ = u2f2(vv.w); \
    acc[0] += t0_.x; acc[1] += t0_.y; acc[2] += t1_.x; acc[3] += t1_.y; \
    acc[4] += t2_.x; acc[5] += t2_.y; acc[6] += t3_.x; acc[7] += t3_.y; }

template <int MODE>
__global__ __launch_bounds__(128) void agg_kernel(const __half* __restrict__ Yh,
                                                  const float* __restrict__ bias,
                                                  __half* __restrict__ xbuf,
                                                  float* __restrict__ out2) {
    int gw = (blockIdx.x * 128 + threadIdx.x) >> 5;
    if (gw >= NN) return;
    int lane = threadIdx.x & 31;
    int h = lane >> 4, q = lane & 15;
    int beg = g_rowptr[gw], end = g_rowptr[gw + 1];
    float nm = g_norm[gw];
    const int* __restrict__ col = g_col;
    const uint4* __restrict__ Y16 = (const uint4*)Yh;  // 16 uint4 per row

    float acc[8];
#pragma unroll
    for (int i = 0; i < 8; i++) acc[i] = 0.f;

    int e = beg;
    for (; e + 7 < end; e += 8) {
        int s0 = col[e + h], s1 = col[e + 2 + h], s2 = col[e + 4 + h], s3 = col[e + 6 + h];
        uint4 v0 = Y16[(size_t)s0 * 16 + q];
        uint4 v1 = Y16[(size_t)s1 * 16 + q];
        uint4 v2 = Y16[(size_t)s2 * 16 + q];
        uint4 v3 = Y16[(size_t)s3 * 16 + q];
        ACC8(v0) ACC8(v1) ACC8(v2) ACC8(v3)
    }
    for (; e + 1 < end; e += 2) {
        int s = col[e + h];
        uint4 v = Y16[(size_t)s * 16 + q];
        ACC8(v)
    }
    // combine the two half-warp partial sums
#pragma unroll
    for (int i = 0; i < 8; i++) acc[i] += __shfl_xor_sync(0xffffffffu, acc[i], 16);
    // leftover single edge: both duplicated halves add the same row once
    if (e < end) {
        int s = col[e];
        uint4 v = Y16[(size_t)s * 16 + q];
        ACC8(v)
    }
    // self-loop term
    {
        uint4 sv = Y16[(size_t)gw * 16 + q];
        ACC8(sv)
    }

    float4 b0 = *(const float4*)(bias + q * 8);
    float4 b1 = *(const float4*)(bias + q * 8 + 4);
    float o[8];
    o[0] = acc[0] * nm + b0.x; o[1] = acc[1] * nm + b0.y;
    o[2] = acc[2] * nm + b0.z; o[3] = acc[3] * nm + b0.w;
    o[4] = acc[4] * nm + b1.x; o[5] = acc[5] * nm + b1.y;
    o[6] = acc[6] * nm + b1.z; o[7] = acc[7] * nm + b1.w;
    float nv[8];
#pragma unroll
    for (int i = 0; i < 8; i++) nv[i] = lk(o[i]);
    if constexpr (MODE != 0) {
        uint4 xr = ((const uint4*)xbuf)[(size_t)gw * 16 + q];
        float2 x0 = u2f2(xr.x), x1 = u2f2(xr.y), x2 = u2f2(xr.z), x3 = u2f2(xr.w);
        nv[0] = (x0.x + nv[0]) * 0.5f; nv[1] = (x0.y + nv[1]) * 0.5f;
        nv[2] = (x1.x + nv[2]) * 0.5f; nv[3] = (x1.y + nv[3]) * 0.5f;
        nv[4] = (x2.x + nv[4]) * 0.5f; nv[5] = (x2.y + nv[5]) * 0.5f;
        nv[6] = (x3.x + nv[6]) * 0.5f; nv[7] = (x3.y + nv[7]) * 0.5f;
        if constexpr (MODE == 3) {
            // fp32 mirror: row = 32 float4; lane writes float4 #(2q+h)
            float4 w4 = make_float4(nv[h * 4], nv[h * 4 + 1], nv[h * 4 + 2], nv[h * 4 + 3]);
            ((float4*)out2)[(size_t)gw * 32 + q * 2 + h] = w4;
        }
    }
    if (h == 0) {
        __half2 p0 = __floats2half2_rn(nv[0], nv[1]);
        __half2 p1 = __floats2half2_rn(nv[2], nv[3]);
        __half2 p2 = __floats2half2_rn(nv[4], nv[5]);
        __half2 p3 = __floats2half2_rn(nv[6], nv[7]);
        uint4 pk;
        pk.x = *reinterpret_cast<unsigned*>(&p0);
        pk.y = *reinterpret_cast<unsigned*>(&p1);
        pk.z = *reinterpret_cast<unsigned*>(&p2);
        pk.w = *reinterpret_cast<unsigned*>(&p3);
        ((uint4*)xbuf)[(size_t)gw * 16 + q] = pk;
    }
}

// ---------------- final aggregation (64-wide): quad-edge uint4 gather ------------
__global__ __launch_bounds__(128) void agg64_kernel(const __half* __restrict__ Yh,
                                                    const float* __restrict__ bias,
                                                    float* __restrict__ outp) {
    int gw = (blockIdx.x * 128 + threadIdx.x) >> 5;
    if (gw >= NN) return;
    int lane = threadIdx.x & 31;
    int h = lane >> 3, q = lane & 7;   // 4 quarter-warps, 8 lanes each
    int beg = g_rowptr[gw], end = g_rowptr[gw + 1];
    float nm = g_norm[gw];
    const int* __restrict__ col = g_col;
    const uint4* __restrict__ Y8 = (const uint4*)Yh;  // 8 uint4 per row

    float acc[8];
#pragma unroll
    for (int i = 0; i < 8; i++) acc[i] = 0.f;

    int e = beg;
    for (; e + 15 < end; e += 16) {
        int s0 = col[e + h], s1 = col[e + 4 + h], s2 = col[e + 8 + h], s3 = col[e + 12 + h];
        uint4 v0 = Y8[(size_t)s0 * 8 + q];
        uint4 v1 = Y8[(size_t)s1 * 8 + q];
        uint4 v2 = Y8[(size_t)s2 * 8 + q];
        uint4 v3 = Y8[(size_t)s3 * 8 + q];
        ACC8(v0) ACC8(v1) ACC8(v2) ACC8(v3)
    }
    for (; e + 3 < end; e += 4) {
        int s = col[e + h];
        uint4 v = Y8[(size_t)s * 8 + q];
        ACC8(v)
    }
#pragma unroll
    for (int i = 0; i < 8; i++) acc[i] += __shfl_xor_sync(0xffffffffu, acc[i], 8);
#pragma unroll
    for (int i = 0; i < 8; i++) acc[i] += __shfl_xor_sync(0xffffffffu, acc[i], 16);
    // leftover 1-3 edges: all (duplicated) lanes add each row once
    for (; e < end; e++) {
        int s = col[e];
        uint4 v = Y8[(size_t)s * 8 + q];
        ACC8(v)
    }
    // self
    {
        uint4 sv = Y8[(size_t)gw * 8 + q];
        ACC8(sv)
    }

    float4 b0 = *(const float4*)(bias + q * 8);
    float4 b1 = *(const float4*)(bias + q * 8 + 4);
    float nv[8];
    nv[0] = acc[0] * nm + b0.x; nv[1] = acc[1] * nm + b0.y;
    nv[2] = acc[2] * nm + b0.z; nv[3] = acc[3] * nm + b0.w;
    nv[4] = acc[4] * nm + b1.x; nv[5] = acc[5] * nm + b1.y;
    nv[6] = acc[6] * nm + b1.z; nv[7] = acc[7] * nm + b1.w;
    if (h < 2) {
        // fp32 row = 16 float4; lane writes float4 #(2q+h)
        float4 w4 = make_float4(nv[h * 4], nv[h * 4 + 1], nv[h * 4 + 2], nv[h * 4 + 3]);
        ((float4*)outp)[(size_t)gw * 16 + q * 2 + h] = w4;
    }
}
#undef ACC8

// ---------------- launch ----------------
extern "C" void kernel_launch(void* const* d_in, const int* in_sizes, int n_in,
                              void* d_out, int out_size) {
    const float* inputs = (const float*)d_in[0];
    const int*   edges  = (const int*)d_in[1];
    const float* b_in   = (const float*)d_in[3];
    const float* b1     = (const float*)d_in[5];
    const float* b2     = (const float*)d_in[7];
    const float* b_out  = (const float*)d_in[9];
    float* out = (float*)d_out;

    const int* src = edges;
    const int* dst = edges + NE;

    void *pyh, *phh, *pxh, *pwh, *pwl, *pcnt;
    cudaGetSymbolAddress(&pyh, g_yh);
    cudaGetSymbolAddress(&phh, g_hh);
    cudaGetSymbolAddress(&pxh, g_xh);
    cudaGetSymbolAddress(&pwh, g_wh);
    cudaGetSymbolAddress(&pwl, g_wl);
    cudaGetSymbolAddress(&pcnt, g_cnt);
    __half* yh = (__half*)pyh;
    __half* hh = (__half*)phh;
    __half* xh = (__half*)pxh;
    __half* wh = (__half*)pwh;
    __half* wl = (__half*)pwl;

    // single-stage smem: (A 128 + Bh BN + Bl BN) rows * 136 halves
    const int SM128 = (128 + 2 * 128) * 136 * 2;  // 104448 B
    const int SM64  = (128 + 2 * 64) * 136 * 2;   //  69632 B
    cudaFuncSetAttribute(gemm_tc_kernel<128, float>,
                         cudaFuncAttributeMaxDynamicSharedMemorySize, SM128);
    cudaFuncSetAttribute(gemm_tc_kernel<128, __half>,
                         cudaFuncAttributeMaxDynamicSharedMemorySize, SM128);
    cudaFuncSetAttribute(gemm_tc_kernel<64, __half>,
                         cudaFuncAttributeMaxDynamicSharedMemorySize, SM64);

    const int GE = (NE + 255) / 256;
    const int GG = (NN + 127) / 128;       // gemm blocks
    const int GA = (NN * 32 + 127) / 128;  // agg blocks (warp/node, 128-thr blocks)
    const int GW = (NMAT * HD * HD + 255) / 256;
    const size_t WSTEP = (size_t)HD * HD;

    // weight split/transpose + CSR build
    prep_w_kernel<<<GW, 256>>>((const float*)d_in[2], (const float*)d_in[4],
                               (const float*)d_in[6], (const float*)d_in[8]);
    cudaMemsetAsync(pcnt, 0, NN * sizeof(int));
    count_kernel<<<GE, 256>>>(dst);
    scan_blocks_kernel<<<NSB, 1024>>>();
    scan_fix_kernel<<<NSB, 1024>>>();
    fill_kernel<<<GE, 256>>>(src, dst);

    // input conv
    gemm_tc_kernel<128, float><<<GG, 256, SM128>>>(inputs, wh, wl, yh);
    agg_kernel<0><<<GA, 128>>>(yh, b_in, xh, nullptr);

    // 6 residual blocks; last one mirrors fp32 x into d_out's second half
    for (int i = 0; i < 6; i++) {
        gemm_tc_kernel<128, __half><<<GG, 256, SM128>>>(xh, wh + (size_t)(1 + i) * WSTEP,
                                                        wl + (size_t)(1 + i) * WSTEP, yh);
        agg_kernel<0><<<GA, 128>>>(yh, b1 + (size_t)i * HD, hh, nullptr);
        gemm_tc_kernel<128, __half><<<GG, 256, SM128>>>(hh, wh + (size_t)(7 + i) * WSTEP,
                                                        wl + (size_t)(7 + i) * WSTEP, yh);
        if (i < 5)
            agg_kernel<1><<<GA, 128>>>(yh, b2 + (size_t)i * HD, xh, nullptr);
        else
            agg_kernel<3><<<GA, 128>>>(yh, b2 + (size_t)i * HD, xh,
                                       out + (size_t)NN * 64);
    }

    // output conv (no activation), writes first N*64 floats of d_out
    gemm_tc_kernel<64, __half><<<GG, 256, SM64>>>(xh, wh + (size_t)13 * WSTEP,
                                                  wl + (size_t)13 * WSTEP, yh);
    agg64_kernel<<<GA, 128>>>(yh, b_out, out);
}

// round 12
// speedup vs baseline: 1.1341x; 1.1341x over previous
#include <cuda_runtime.h>
#include <cuda_fp16.h>
#include <cuda_bf16.h>

#define NN 50000
#define NE 800000
#define HD 128
#define NMAT 14
#define NSB 49   // scan blocks: ceil(50000/1024)

// ---------------- device scratch (no allocations allowed) ----------------
__device__ __half  g_yh[(size_t)NN * HD];   // fp16 messages (GEMM output, norm-scaled)
__device__ __half  g_hh[(size_t)NN * HD];   // fp16 block intermediate h
__device__ __half  g_xh[(size_t)NN * HD];   // fp16 running x master
__device__ float   g_norm[NN];
__device__ int     g_rowptr[NN + 1];
__device__ int     g_cnt[NN];
__device__ int     g_off[NN];
__device__ int     g_col[NE];
__device__ int     g_bsum[NSB];             // raw per-block totals
__device__ __half  g_wh[(size_t)NMAT * HD * HD];  // weights, n-major, fp16 hi
__device__ __half  g_wl[(size_t)NMAT * HD * HD];  // fp16 lo residual

__device__ __forceinline__ float lk(float v) { return v >= 0.f ? v : 0.01f * v; }

__device__ __forceinline__ float2 u2f2(unsigned u) {
    __half2 h = *reinterpret_cast<__half2*>(&u);
    return __half22float2(h);
}

// ---------------- CSR build ----------------
__global__ void count_kernel(const int* __restrict__ dst) {
    int e = blockIdx.x * blockDim.x + threadIdx.x;
    if (e < NE) atomicAdd(&g_cnt[dst[e]], 1);
}

__global__ __launch_bounds__(1024) void scan_blocks_kernel() {
    __shared__ int ws[32];
    int tid = threadIdx.x, lane = tid & 31, wid = tid >> 5;
    int i = blockIdx.x * 1024 + tid;
    int v = (i < NN) ? g_cnt[i] : 0;
    int x = v;
#pragma unroll
    for (int d = 1; d < 32; d <<= 1) {
        int t = __shfl_up_sync(0xffffffffu, x, d);
        if (lane >= d) x += t;
    }
    if (lane == 31) ws[wid] = x;
    __syncthreads();
    if (wid == 0) {
        int s = ws[lane];
#pragma unroll
        for (int d = 1; d < 32; d <<= 1) {
            int t = __shfl_up_sync(0xffffffffu, s, d);
            if (lane >= d) s += t;
        }
        ws[lane] = s;
    }
    __syncthreads();
    int off = wid ? ws[wid - 1] : 0;
    if (i < NN) g_rowptr[i] = off + x - v;
    if (tid == 1023) g_bsum[blockIdx.x] = off + x;
}

__global__ __launch_bounds__(1024) void scan_fix_kernel() {
    __shared__ int s_off;
    int tid = threadIdx.x;
    if (tid < 32) {
        int b = blockIdx.x;
        int t0 = (tid < NSB && tid < b) ? g_bsum[tid] : 0;
        int t1 = (tid + 32 < NSB && tid + 32 < b) ? g_bsum[tid + 32] : 0;
        int s = t0 + t1;
#pragma unroll
        for (int d = 16; d >= 1; d >>= 1) s += __shfl_xor_sync(0xffffffffu, s, d);
        if (tid == 0) s_off = s;
    }
    __syncthreads();
    int i = blockIdx.x * 1024 + tid;
    if (i < NN) {
        int r = g_rowptr[i] + s_off;
        g_rowptr[i] = r;
        g_off[i] = r;
        g_norm[i] = rsqrtf(1.0f + (float)g_cnt[i]);
    }
    if (blockIdx.x == 0 && tid == 0) g_rowptr[NN] = NE;
}

__global__ void fill_kernel(const int* __restrict__ src, const int* __restrict__ dst) {
    int e = blockIdx.x * blockDim.x + threadIdx.x;
    if (e < NE) {
        int d = dst[e];
        int p = atomicAdd(&g_off[d], 1);
        g_col[p] = src[e];
    }
}

// ---------------- weight prep: transpose to n-major, split fp32 -> fp16 hi/lo ----
__global__ void prep_w_kernel(const float* __restrict__ w_in, const float* __restrict__ w1,
                              const float* __restrict__ w2, const float* __restrict__ w_out) {
    int idx = blockIdx.x * blockDim.x + threadIdx.x;
    if (idx >= NMAT * HD * HD) return;
    int mat = idx >> 14;
    int rem = idx & 16383;
    int n = rem >> 7, k = rem & 127;
    float v;
    if (mat == 0)       v = w_in[k * HD + n];
    else if (mat <= 6)  v = w1[(size_t)(mat - 1) * HD * HD + k * HD + n];
    else if (mat <= 12) v = w2[(size_t)(mat - 7) * HD * HD + k * HD + n];
    else                v = (n < 64) ? w_out[k * 64 + n] : 0.f;
    __half hi = __float2half_rn(v);
    __half lo = __float2half_rn(v - __half2float(hi));
    g_wh[idx] = hi;
    g_wl[idx] = lo;
}

// ---------------- fp16 MMA helper (fp32 accumulate) ----------------
__device__ __forceinline__ void mma_f16(float* c, unsigned a0, unsigned a1, unsigned a2,
                                        unsigned a3, unsigned b0, unsigned b1) {
    asm volatile(
        "mma.sync.aligned.m16n8k16.row.col.f32.f16.f16.f32 "
        "{%0,%1,%2,%3}, {%4,%5,%6,%7}, {%8,%9}, {%0,%1,%2,%3};"
        : "+f"(c[0]), "+f"(c[1]), "+f"(c[2]), "+f"(c[3])
        : "r"(a0), "r"(a1), "r"(a2), "r"(a3), "r"(b0), "r"(b1));
}

// ---------------- tensor-core GEMM, double-buffered smem (1 sync/stage) --------
// Y = half((A@W)*norm), K=128. A fp32->fp16 or fp16; W split fp16 hi/lo.
template <int BN, typename AT>
__global__ __launch_bounds__(256) void gemm_tc_kernel(const AT* __restrict__ A,
                                                      const __half* __restrict__ Wh,
                                                      const __half* __restrict__ Wl,
                                                      __half* __restrict__ Yh) {
    constexpr int BM = 128, BK = 32, K = 128;
    constexpr int WN = BN / 4;   // 32 or 16
    constexpr int NT = WN / 8;   // 4 or 2
    constexpr int SA = 40;
    constexpr int ASZ = BM * SA;       // per-buffer A halves
    constexpr int BSZ = BN * SA;       // per-buffer B halves
    extern __shared__ __half smem[];
    __half* sA  = smem;                // 2 * ASZ
    __half* sBh = smem + 2 * ASZ;      // 2 * BSZ
    __half* sBl = sBh + 2 * BSZ;       // 2 * BSZ

    const int tid = threadIdx.x, lane = tid & 31, wid = tid >> 5;
    const int g = lane >> 2, t = lane & 3;
    const int wm = (wid & 1) * 64, wn = (wid >> 1) * WN;
    const int m0 = blockIdx.x * BM;

    float acc[4][NT][4];
#pragma unroll
    for (int i = 0; i < 4; i++)
#pragma unroll
        for (int j = 0; j < NT; j++)
#pragma unroll
            for (int q = 0; q < 4; q++) acc[i][j][q] = 0.f;

    float4 vaf[4];
    uint2  vah[4];
    uint4 vbh[2], vbl[2];

    auto loadA = [&](int k0) {
#pragma unroll
        for (int l = 0; l < 4; l++) {
            int idx = tid + l * 256, r = idx >> 3, c = idx & 7;
            if constexpr (sizeof(AT) == 4) {
                vaf[l] = make_float4(0.f, 0.f, 0.f, 0.f);
                if (m0 + r < NN)
                    vaf[l] = *(const float4*)((const float*)A + (size_t)(m0 + r) * K + k0 + c * 4);
            } else {
                vah[l] = make_uint2(0u, 0u);
                if (m0 + r < NN)
                    vah[l] = *(const uint2*)((const __half*)A + (size_t)(m0 + r) * K + k0 + c * 4);
            }
        }
    };
    auto loadB = [&](int k0) {
        if constexpr (BN == 128) {
            int n = tid >> 1, kh = (tid & 1) * 16;
            vbh[0] = *(const uint4*)&Wh[(size_t)n * K + k0 + kh];
            vbh[1] = *(const uint4*)&Wh[(size_t)n * K + k0 + kh + 8];
            vbl[0] = *(const uint4*)&Wl[(size_t)n * K + k0 + kh];
            vbl[1] = *(const uint4*)&Wl[(size_t)n * K + k0 + kh + 8];
        } else {
            int n = tid >> 2, kh = (tid & 3) * 8;
            vbh[0] = *(const uint4*)&Wh[(size_t)n * K + k0 + kh];
            vbl[0] = *(const uint4*)&Wl[(size_t)n * K + k0 + kh];
        }
    };
    auto storeTiles = [&](int buf) {
        __half* dA  = sA  + buf * ASZ;
        __half* dBh = sBh + buf * BSZ;
        __half* dBl = sBl + buf * BSZ;
#pragma unroll
        for (int l = 0; l < 4; l++) {
            int idx = tid + l * 256, r = idx >> 3, c = idx & 7;
            if constexpr (sizeof(AT) == 4) {
                float4 v = vaf[l];
                __half2 h01 = __floats2half2_rn(v.x, v.y);
                __half2 h23 = __floats2half2_rn(v.z, v.w);
                *(__half2*)&dA[r * SA + c * 4]     = h01;
                *(__half2*)&dA[r * SA + c * 4 + 2] = h23;
            } else {
                *(uint2*)&dA[r * SA + c * 4] = vah[l];
            }
        }
        if constexpr (BN == 128) {
            int n = tid >> 1, kh = (tid & 1) * 16;
            *(uint4*)&dBh[n * SA + kh]     = vbh[0];
            *(uint4*)&dBh[n * SA + kh + 8] = vbh[1];
            *(uint4*)&dBl[n * SA + kh]     = vbl[0];
            *(uint4*)&dBl[n * SA + kh + 8] = vbl[1];
        } else {
            int n = tid >> 2, kh = (tid & 3) * 8;
            *(uint4*)&dBh[n * SA + kh] = vbh[0];
            *(uint4*)&dBl[n * SA + kh] = vbl[0];
        }
    };

    loadA(0);
    loadB(0);
    storeTiles(0);
    __syncthreads();
#pragma unroll
    for (int s = 0; s < 4; s++) {
        if (s < 3) { loadA((s + 1) * BK); loadB((s + 1) * BK); }
        const int buf = s & 1;
        const __half* cA  = sA  + buf * ASZ;
        const __half* cBh = sBh + buf * BSZ;
        const __half* cBl = sBl + buf * BSZ;
#pragma unroll
        for (int kk = 0; kk < BK; kk += 16) {
            unsigned bh[NT][2], bl[NT][2];
#pragma unroll
            for (int nt = 0; nt < NT; nt++) {
                int n = wn + nt * 8 + g;
                bh[nt][0] = *(const unsigned*)&cBh[n * SA + kk + 2 * t];
                bh[nt][1] = *(const unsigned*)&cBh[n * SA + kk + 2 * t + 8];
                bl[nt][0] = *(const unsigned*)&cBl[n * SA + kk + 2 * t];
                bl[nt][1] = *(const unsigned*)&cBl[n * SA + kk + 2 * t + 8];
            }
#pragma unroll
            for (int mt = 0; mt < 4; mt++) {
                int m = wm + mt * 16 + g;
                unsigned a0 = *(const unsigned*)&cA[m * SA + kk + 2 * t];
                unsigned a1 = *(const unsigned*)&cA[(m + 8) * SA + kk + 2 * t];
                unsigned a2 = *(const unsigned*)&cA[m * SA + kk + 2 * t + 8];
                unsigned a3 = *(const unsigned*)&cA[(m + 8) * SA + kk + 2 * t + 8];
#pragma unroll
                for (int nt = 0; nt < NT; nt++) {
                    mma_f16(acc[mt][nt], a0, a1, a2, a3, bh[nt][0], bh[nt][1]);
                    mma_f16(acc[mt][nt], a0, a1, a2, a3, bl[nt][0], bl[nt][1]);
                }
            }
        }
        if (s < 3) {
            storeTiles(1 - buf);
            __syncthreads();
        }
    }

#pragma unroll
    for (int mt = 0; mt < 4; mt++) {
        int r0 = m0 + wm + mt * 16 + g, r1 = r0 + 8;
        float n0 = (r0 < NN) ? g_norm[r0] : 0.f;
        float n1 = (r1 < NN) ? g_norm[r1] : 0.f;
#pragma unroll
        for (int nt = 0; nt < NT; nt++) {
            int col = wn + nt * 8 + 2 * t;
            if (r0 < NN) {
                __half2 h = __floats2half2_rn(acc[mt][nt][0] * n0, acc[mt][nt][1] * n0);
                *(__half2*)(Yh + (size_t)r0 * BN + col) = h;
            }
            if (r1 < NN) {
                __half2 h = __floats2half2_rn(acc[mt][nt][2] * n1, acc[mt][nt][3] * n1);
                *(__half2*)(Yh + (size_t)r1 * BN + col) = h;
            }
        }
    }
}

// ---------------- Aggregation: one warp per node, unroll-8 uint2 gather ---------
// Index batches software-pipelined: next 8 indices load during current gathers.
// o = norm[n]*(y[n] + sum y[src]) + bias
// MODE 0: leaky(o) -> half buffer   MODE 1: x=(x+leaky(o))/2 fp16 in place
// MODE 3: MODE 1 + unrounded fp32 mirror to out2
template <int MODE>
__global__ __launch_bounds__(128) void agg_kernel(const __half* __restrict__ Yh,
                                                  const float* __restrict__ bias,
                                                  __half* __restrict__ xbuf,
                                                  float* __restrict__ out2) {
    int gw = (blockIdx.x * 128 + threadIdx.x) >> 5;
    if (gw >= NN) return;
    int lane = threadIdx.x & 31;
    int beg = g_rowptr[gw], end = g_rowptr[gw + 1];
    float nm = g_norm[gw];
    const int* __restrict__ col = g_col;
    const uint2* Y4 = (const uint2*)Yh;
    uint2 sv = Y4[(size_t)gw * 32 + lane];
    float2 f0 = u2f2(sv.x), f1 = u2f2(sv.y);
    float4 acc = make_float4(f0.x, f0.y, f1.x, f1.y);
    int e = beg;
#define ACCV(vv) { float2 p_ = u2f2(vv.x), q_ = u2f2(vv.y); \
                   acc.x += p_.x; acc.y += p_.y; acc.z += q_.x; acc.w += q_.y; }
    int s[8];
    if (e + 7 < end) {
#pragma unroll
        for (int j = 0; j < 8; j++) s[j] = col[e + j];
    }
    for (; e + 7 < end; ) {
        int c0 = s[0], c1 = s[1], c2 = s[2], c3 = s[3];
        int c4 = s[4], c5 = s[5], c6 = s[6], c7 = s[7];
        int en = e + 8;
        if (en + 7 < end) {
#pragma unroll
            for (int j = 0; j < 8; j++) s[j] = col[en + j];
        }
        uint2 v0 = Y4[(size_t)c0 * 32 + lane];
        uint2 v1 = Y4[(size_t)c1 * 32 + lane];
        uint2 v2 = Y4[(size_t)c2 * 32 + lane];
        uint2 v3 = Y4[(size_t)c3 * 32 + lane];
        uint2 v4 = Y4[(size_t)c4 * 32 + lane];
        uint2 v5 = Y4[(size_t)c5 * 32 + lane];
        uint2 v6 = Y4[(size_t)c6 * 32 + lane];
        uint2 v7 = Y4[(size_t)c7 * 32 + lane];
        ACCV(v0) ACCV(v1) ACCV(v2) ACCV(v3)
        ACCV(v4) ACCV(v5) ACCV(v6) ACCV(v7)
        e = en;
    }
    for (; e + 1 < end; e += 2) {
        int c0 = col[e], c1 = col[e + 1];
        uint2 v0 = Y4[(size_t)c0 * 32 + lane];
        uint2 v1 = Y4[(size_t)c1 * 32 + lane];
        ACCV(v0) ACCV(v1)
    }
    if (e < end) {
        uint2 v = Y4[(size_t)col[e] * 32 + lane];
        ACCV(v)
    }
#undef ACCV
    float4 b = ((const float4*)bias)[lane];
    float4 o = make_float4(acc.x * nm + b.x, acc.y * nm + b.y,
                           acc.z * nm + b.z, acc.w * nm + b.w);
    size_t idx = (size_t)gw * 32 + lane;
    float4 l4 = make_float4(lk(o.x), lk(o.y), lk(o.z), lk(o.w));
    float4 nv;
    if constexpr (MODE == 0) {
        nv = l4;
    } else {
        uint2 xr = ((const uint2*)xbuf)[idx];
        float2 x0 = u2f2(xr.x), x1 = u2f2(xr.y);
        nv = make_float4((x0.x + l4.x) * 0.5f, (x0.y + l4.y) * 0.5f,
                         (x1.x + l4.z) * 0.5f, (x1.y + l4.w) * 0.5f);
        if constexpr (MODE == 3) ((float4*)out2)[idx] = nv;
    }
    uint2 p;
    __half2 h01 = __floats2half2_rn(nv.x, nv.y);
    __half2 h23 = __floats2half2_rn(nv.z, nv.w);
    p.x = *reinterpret_cast<unsigned*>(&h01);
    p.y = *reinterpret_cast<unsigned*>(&h23);
    ((uint2*)xbuf)[idx] = p;
}

// ---------------- final aggregation (output conv, D=64, no activation) --------
__global__ __launch_bounds__(128) void agg64_kernel(const __half* __restrict__ Yh,
                                                    const float* __restrict__ bias,
                                                    float* __restrict__ outp) {
    int gw = (blockIdx.x * 128 + threadIdx.x) >> 5;
    if (gw >= NN) return;
    int lane = threadIdx.x & 31;
    int beg = g_rowptr[gw], end = g_rowptr[gw + 1];
    float nm = g_norm[gw];
    const int* __restrict__ col = g_col;
    const unsigned* Y2 = (const unsigned*)Yh;
    float2 acc = u2f2(Y2[(size_t)gw * 32 + lane]);
    int e = beg;
    for (; e + 7 < end; e += 8) {
        int s0 = col[e],     s1 = col[e + 1], s2 = col[e + 2], s3 = col[e + 3];
        int s4 = col[e + 4], s5 = col[e + 5], s6 = col[e + 6], s7 = col[e + 7];
        float2 v0 = u2f2(Y2[(size_t)s0 * 32 + lane]);
        float2 v1 = u2f2(Y2[(size_t)s1 * 32 + lane]);
        float2 v2 = u2f2(Y2[(size_t)s2 * 32 + lane]);
        float2 v3 = u2f2(Y2[(size_t)s3 * 32 + lane]);
        float2 v4 = u2f2(Y2[(size_t)s4 * 32 + lane]);
        float2 v5 = u2f2(Y2[(size_t)s5 * 32 + lane]);
        float2 v6 = u2f2(Y2[(size_t)s6 * 32 + lane]);
        float2 v7 = u2f2(Y2[(size_t)s7 * 32 + lane]);
        acc.x += ((v0.x + v1.x) + (v2.x + v3.x)) + ((v4.x + v5.x) + (v6.x + v7.x));
        acc.y += ((v0.y + v1.y) + (v2.y + v3.y)) + ((v4.y + v5.y) + (v6.y + v7.y));
    }
    for (; e < end; e++) {
        float2 v = u2f2(Y2[(size_t)col[e] * 32 + lane]);
        acc.x += v.x; acc.y += v.y;
    }
    float2 b = ((const float2*)bias)[lane];
    ((float2*)outp)[(size_t)gw * 32 + lane] =
        make_float2(acc.x * nm + b.x, acc.y * nm + b.y);
}

// ---------------- launch ----------------
extern "C" void kernel_launch(void* const* d_in, const int* in_sizes, int n_in,
                              void* d_out, int out_size) {
    const float* inputs = (const float*)d_in[0];
    const int*   edges  = (const int*)d_in[1];
    const float* b_in   = (const float*)d_in[3];
    const float* b1     = (const float*)d_in[5];
    const float* b2     = (const float*)d_in[7];
    const float* b_out  = (const float*)d_in[9];
    float* out = (float*)d_out;

    const int* src = edges;
    const int* dst = edges + NE;

    void *pyh, *phh, *pxh, *pwh, *pwl, *pcnt;
    cudaGetSymbolAddress(&pyh, g_yh);
    cudaGetSymbolAddress(&phh, g_hh);
    cudaGetSymbolAddress(&pxh, g_xh);
    cudaGetSymbolAddress(&pwh, g_wh);
    cudaGetSymbolAddress(&pwl, g_wl);
    cudaGetSymbolAddress(&pcnt, g_cnt);
    __half* yh = (__half*)pyh;
    __half* hh = (__half*)phh;
    __half* xh = (__half*)pxh;
    __half* wh = (__half*)pwh;
    __half* wl = (__half*)pwl;

    // dynamic smem: 2 buffers of (A 128*40 + Bh BN*40 + Bl BN*40) halves
    const int SM128 = 2 * (128 * 40 + 2 * 128 * 40) * 2;  // 61440 B
    const int SM64  = 2 * (128 * 40 + 2 * 64 * 40) * 2;   // 40960 B
    cudaFuncSetAttribute(gemm_tc_kernel<128, float>,
                         cudaFuncAttributeMaxDynamicSharedMemorySize, SM128);
    cudaFuncSetAttribute(gemm_tc_kernel<128, __half>,
                         cudaFuncAttributeMaxDynamicSharedMemorySize, SM128);
    cudaFuncSetAttribute(gemm_tc_kernel<64, __half>,
                         cudaFuncAttributeMaxDynamicSharedMemorySize, SM64);

    const int GE = (NE + 255) / 256;
    const int GG = (NN + 127) / 128;       // gemm blocks
    const int GA = (NN * 32 + 127) / 128;  // agg blocks (warp/node, 128-thr blocks)
    const int GW = (NMAT * HD * HD + 255) / 256;
    const size_t WSTEP = (size_t)HD * HD;

    // weight split/transpose + CSR build
    prep_w_kernel<<<GW, 256>>>((const float*)d_in[2], (const float*)d_in[4],
                               (const float*)d_in[6], (const float*)d_in[8]);
    cudaMemsetAsync(pcnt, 0, NN * sizeof(int));
    count_kernel<<<GE, 256>>>(dst);
    scan_blocks_kernel<<<NSB, 1024>>>();
    scan_fix_kernel<<<NSB, 1024>>>();
    fill_kernel<<<GE, 256>>>(src, dst);

    // input conv
    gemm_tc_kernel<128, float><<<GG, 256, SM128>>>(inputs, wh, wl, yh);
    agg_kernel<0><<<GA, 128>>>(yh, b_in, xh, nullptr);

    // 6 residual blocks; last one mirrors fp32 x into d_out's second half
    for (int i = 0; i < 6; i++) {
        gemm_tc_kernel<128, __half><<<GG, 256, SM128>>>(xh, wh + (size_t)(1 + i) * WSTEP,
                                                        wl + (size_t)(1 + i) * WSTEP, yh);
        agg_kernel<0><<<GA, 128>>>(yh, b1 + (size_t)i * HD, hh, nullptr);
        gemm_tc_kernel<128, __half><<<GG, 256, SM128>>>(hh, wh + (size_t)(7 + i) * WSTEP,
                                                        wl + (size_t)(7 + i) * WSTEP, yh);
        if (i < 5)
            agg_kernel<1><<<GA, 128>>>(yh, b2 + (size_t)i * HD, xh, nullptr);
        else
            agg_kernel<3><<<GA, 128>>>(yh, b2 + (size_t)i * HD, xh,
                                       out + (size_t)NN * 64);
    }

    // output conv (no activation), writes first N*64 floats of d_out
    gemm_tc_kernel<64, __half><<<GG, 256, SM64>>>(xh, wh + (size_t)13 * WSTEP,
                                                  wl + (size_t)13 * WSTEP, yh);
    agg64_kernel<<<GA, 128>>>(yh, b_out, out);
}

// round 13
// speedup vs baseline: 1.1740x; 1.0352x over previous
#include <cuda_runtime.h>
#include <cuda_fp16.h>
#include <cuda_bf16.h>

#define NN 50000
#define NE 800000
#define HD 128
#define NMAT 14
#define NSB 49   // scan blocks: ceil(50000/1024)

// ---------------- device scratch (no allocations allowed) ----------------
__device__ __half  g_yh[(size_t)NN * HD];   // fp16 messages (GEMM output, norm-scaled)
__device__ __half  g_hh[(size_t)NN * HD];   // fp16 block intermediate h
__device__ __half  g_xh[(size_t)NN * HD];   // fp16 running x master
__device__ float   g_norm[NN];
__device__ int     g_rowptr[NN + 1];
__device__ int     g_cnt[NN];
__device__ int     g_off[NN];
__device__ int     g_col[NE];
__device__ int     g_bsum[NSB];             // raw per-block totals
__device__ __half  g_wh[(size_t)NMAT * HD * HD];  // weights, n-major, fp16 hi
__device__ __half  g_wl[(size_t)NMAT * HD * HD];  // fp16 lo residual

__device__ __forceinline__ float lk(float v) { return v >= 0.f ? v : 0.01f * v; }

__device__ __forceinline__ float2 u2f2(unsigned u) {
    __half2 h = *reinterpret_cast<__half2*>(&u);
    return __half22float2(h);
}

// ---------------- CSR build ----------------
__global__ void count_kernel(const int* __restrict__ dst) {
    int e = blockIdx.x * blockDim.x + threadIdx.x;
    int d = (e < NE) ? dst[e] : 0;          // harness input: safe pre-sync
    cudaGridDependencySynchronize();        // wait for memset of g_cnt
    cudaTriggerProgrammaticLaunchCompletion();
    if (e < NE) atomicAdd(&g_cnt[d], 1);
}

__global__ __launch_bounds__(1024) void scan_blocks_kernel() {
    __shared__ int ws[32];
    int tid = threadIdx.x, lane = tid & 31, wid = tid >> 5;
    int i = blockIdx.x * 1024 + tid;
    cudaGridDependencySynchronize();        // g_cnt dependent
    int v = (i < NN) ? g_cnt[i] : 0;
    int x = v;
#pragma unroll
    for (int d = 1; d < 32; d <<= 1) {
        int t = __shfl_up_sync(0xffffffffu, x, d);
        if (lane >= d) x += t;
    }
    if (lane == 31) ws[wid] = x;
    __syncthreads();
    if (wid == 0) {
        int s = ws[lane];
#pragma unroll
        for (int d = 1; d < 32; d <<= 1) {
            int t = __shfl_up_sync(0xffffffffu, s, d);
            if (lane >= d) s += t;
        }
        ws[lane] = s;
    }
    __syncthreads();
    int off = wid ? ws[wid - 1] : 0;
    if (i < NN) g_rowptr[i] = off + x - v;
    if (tid == 1023) g_bsum[blockIdx.x] = off + x;
    cudaTriggerProgrammaticLaunchCompletion();
}

__global__ __launch_bounds__(1024) void scan_fix_kernel() {
    __shared__ int s_off;
    int tid = threadIdx.x;
    cudaGridDependencySynchronize();        // rowptr/bsum dependent
    if (tid < 32) {
        int b = blockIdx.x;
        int t0 = (tid < NSB && tid < b) ? g_bsum[tid] : 0;
        int t1 = (tid + 32 < NSB && tid + 32 < b) ? g_bsum[tid + 32] : 0;
        int s = t0 + t1;
#pragma unroll
        for (int d = 16; d >= 1; d >>= 1) s += __shfl_xor_sync(0xffffffffu, s, d);
        if (tid == 0) s_off = s;
    }
    __syncthreads();
    int i = blockIdx.x * 1024 + tid;
    if (i < NN) {
        int r = g_rowptr[i] + s_off;
        g_rowptr[i] = r;
        g_off[i] = r;
        g_norm[i] = rsqrtf(1.0f + (float)g_cnt[i]);
    }
    if (blockIdx.x == 0 && tid == 0) g_rowptr[NN] = NE;
    cudaTriggerProgrammaticLaunchCompletion();
}

__global__ void fill_kernel(const int* __restrict__ src, const int* __restrict__ dst) {
    int e = blockIdx.x * blockDim.x + threadIdx.x;
    int s = 0, d = 0;
    if (e < NE) { s = src[e]; d = dst[e]; }  // harness inputs: safe pre-sync
    cudaGridDependencySynchronize();         // g_off dependent
    if (e < NE) {
        int p = atomicAdd(&g_off[d], 1);
        g_col[p] = s;
    }
    cudaTriggerProgrammaticLaunchCompletion();
}

// ---------------- weight prep: transpose to n-major, split fp32 -> fp16 hi/lo ----
__global__ void prep_w_kernel(const float* __restrict__ w_in, const float* __restrict__ w1,
                              const float* __restrict__ w2, const float* __restrict__ w_out) {
    int idx = blockIdx.x * blockDim.x + threadIdx.x;
    if (idx >= NMAT * HD * HD) return;
    int mat = idx >> 14;
    int rem = idx & 16383;
    int n = rem >> 7, k = rem & 127;
    float v;
    if (mat == 0)       v = w_in[k * HD + n];
    else if (mat <= 6)  v = w1[(size_t)(mat - 1) * HD * HD + k * HD + n];
    else if (mat <= 12) v = w2[(size_t)(mat - 7) * HD * HD + k * HD + n];
    else                v = (n < 64) ? w_out[k * 64 + n] : 0.f;
    cudaGridDependencySynchronize();   // guard vs prior graph replay's readers
    __half hi = __float2half_rn(v);
    __half lo = __float2half_rn(v - __half2float(hi));
    g_wh[idx] = hi;
    g_wl[idx] = lo;
    cudaTriggerProgrammaticLaunchCompletion();
}

// ---------------- fp16 MMA helper (fp32 accumulate) ----------------
__device__ __forceinline__ void mma_f16(float* c, unsigned a0, unsigned a1, unsigned a2,
                                        unsigned a3, unsigned b0, unsigned b1) {
    asm volatile(
        "mma.sync.aligned.m16n8k16.row.col.f32.f16.f16.f32 "
        "{%0,%1,%2,%3}, {%4,%5,%6,%7}, {%8,%9}, {%0,%1,%2,%3};"
        : "+f"(c[0]), "+f"(c[1]), "+f"(c[2]), "+f"(c[3])
        : "r"(a0), "r"(a1), "r"(a2), "r"(a3), "r"(b0), "r"(b1));
}

// ---------------- tensor-core GEMM, double-buffered smem (1 sync/stage) --------
// Y = half((A@W)*norm), K=128. A fp32->fp16 or fp16; W split fp16 hi/lo.
// PDL: B tile 0 (weights, written only by prep_w, >=2 launches upstream) loads
// pre-sync; A (fresh agg output) loads post-sync.
template <int BN, typename AT>
__global__ __launch_bounds__(256) void gemm_tc_kernel(const AT* __restrict__ A,
                                                      const __half* __restrict__ Wh,
                                                      const __half* __restrict__ Wl,
                                                      __half* __restrict__ Yh) {
    constexpr int BM = 128, BK = 32, K = 128;
    constexpr int WN = BN / 4;   // 32 or 16
    constexpr int NT = WN / 8;   // 4 or 2
    constexpr int SA = 40;
    constexpr int ASZ = BM * SA;       // per-buffer A halves
    constexpr int BSZ = BN * SA;       // per-buffer B halves
    extern __shared__ __half smem[];
    __half* sA  = smem;                // 2 * ASZ
    __half* sBh = smem + 2 * ASZ;      // 2 * BSZ
    __half* sBl = sBh + 2 * BSZ;       // 2 * BSZ

    const int tid = threadIdx.x, lane = tid & 31, wid = tid >> 5;
    const int g = lane >> 2, t = lane & 3;
    const int wm = (wid & 1) * 64, wn = (wid >> 1) * WN;
    const int m0 = blockIdx.x * BM;

    float acc[4][NT][4];
#pragma unroll
    for (int i = 0; i < 4; i++)
#pragma unroll
        for (int j = 0; j < NT; j++)
#pragma unroll
            for (int q = 0; q < 4; q++) acc[i][j][q] = 0.f;

    float4 vaf[4];
    uint2  vah[4];
    uint4 vbh[2], vbl[2];

    auto loadA = [&](int k0) {
#pragma unroll
        for (int l = 0; l < 4; l++) {
            int idx = tid + l * 256, r = idx >> 3, c = idx & 7;
            if constexpr (sizeof(AT) == 4) {
                vaf[l] = make_float4(0.f, 0.f, 0.f, 0.f);
                if (m0 + r < NN)
                    vaf[l] = *(const float4*)((const float*)A + (size_t)(m0 + r) * K + k0 + c * 4);
            } else {
                vah[l] = make_uint2(0u, 0u);
                if (m0 + r < NN)
                    vah[l] = *(const uint2*)((const __half*)A + (size_t)(m0 + r) * K + k0 + c * 4);
            }
        }
    };
    auto loadB = [&](int k0) {
        if constexpr (BN == 128) {
            int n = tid >> 1, kh = (tid & 1) * 16;
            vbh[0] = *(const uint4*)&Wh[(size_t)n * K + k0 + kh];
            vbh[1] = *(const uint4*)&Wh[(size_t)n * K + k0 + kh + 8];
            vbl[0] = *(const uint4*)&Wl[(size_t)n * K + k0 + kh];
            vbl[1] = *(const uint4*)&Wl[(size_t)n * K + k0 + kh + 8];
        } else {
            int n = tid >> 2, kh = (tid & 3) * 8;
            vbh[0] = *(const uint4*)&Wh[(size_t)n * K + k0 + kh];
            vbl[0] = *(const uint4*)&Wl[(size_t)n * K + k0 + kh];
        }
    };
    auto storeTiles = [&](int buf) {
        __half* dA  = sA  + buf * ASZ;
        __half* dBh = sBh + buf * BSZ;
        __half* dBl = sBl + buf * BSZ;
#pragma unroll
        for (int l = 0; l < 4; l++) {
            int idx = tid + l * 256, r = idx >> 3, c = idx & 7;
            if constexpr (sizeof(AT) == 4) {
                float4 v = vaf[l];
                __half2 h01 = __floats2half2_rn(v.x, v.y);
                __half2 h23 = __floats2half2_rn(v.z, v.w);
                *(__half2*)&dA[r * SA + c * 4]     = h01;
                *(__half2*)&dA[r * SA + c * 4 + 2] = h23;
            } else {
                *(uint2*)&dA[r * SA + c * 4] = vah[l];
            }
        }
        if constexpr (BN == 128) {
            int n = tid >> 1, kh = (tid & 1) * 16;
            *(uint4*)&dBh[n * SA + kh]     = vbh[0];
            *(uint4*)&dBh[n * SA + kh + 8] = vbh[1];
            *(uint4*)&dBl[n * SA + kh]     = vbl[0];
            *(uint4*)&dBl[n * SA + kh + 8] = vbl[1];
        } else {
            int n = tid >> 2, kh = (tid & 3) * 8;
            *(uint4*)&dBh[n * SA + kh] = vbh[0];
            *(uint4*)&dBl[n * SA + kh] = vbl[0];
        }
    };

    loadB(0);                         // independent prologue (weights)
    cudaGridDependencySynchronize();  // wait for A producer
    loadA(0);
    storeTiles(0);
    __syncthreads();
#pragma unroll
    for (int s = 0; s < 4; s++) {
        if (s < 3) { loadA((s + 1) * BK); loadB((s + 1) * BK); }
        const int buf = s & 1;
        const __half* cA  = sA  + buf * ASZ;
        const __half* cBh = sBh + buf * BSZ;
        const __half* cBl = sBl + buf * BSZ;
#pragma unroll
        for (int kk = 0; kk < BK; kk += 16) {
            unsigned bh[NT][2], bl[NT][2];
#pragma unroll
            for (int nt = 0; nt < NT; nt++) {
                int n = wn + nt * 8 + g;
                bh[nt][0] = *(const unsigned*)&cBh[n * SA + kk + 2 * t];
                bh[nt][1] = *(const unsigned*)&cBh[n * SA + kk + 2 * t + 8];
                bl[nt][0] = *(const unsigned*)&cBl[n * SA + kk + 2 * t];
                bl[nt][1] = *(const unsigned*)&cBl[n * SA + kk + 2 * t + 8];
            }
#pragma unroll
            for (int mt = 0; mt < 4; mt++) {
                int m = wm + mt * 16 + g;
                unsigned a0 = *(const unsigned*)&cA[m * SA + kk + 2 * t];
                unsigned a1 = *(const unsigned*)&cA[(m + 8) * SA + kk + 2 * t];
                unsigned a2 = *(const unsigned*)&cA[m * SA + kk + 2 * t + 8];
                unsigned a3 = *(const unsigned*)&cA[(m + 8) * SA + kk + 2 * t + 8];
#pragma unroll
                for (int nt = 0; nt < NT; nt++) {
                    mma_f16(acc[mt][nt], a0, a1, a2, a3, bh[nt][0], bh[nt][1]);
                    mma_f16(acc[mt][nt], a0, a1, a2, a3, bl[nt][0], bl[nt][1]);
                }
            }
        }
        if (s < 3) {
            storeTiles(1 - buf);
            __syncthreads();
        }
    }

#pragma unroll
    for (int mt = 0; mt < 4; mt++) {
        int r0 = m0 + wm + mt * 16 + g, r1 = r0 + 8;
        float n0 = (r0 < NN) ? g_norm[r0] : 0.f;
        float n1 = (r1 < NN) ? g_norm[r1] : 0.f;
#pragma unroll
        for (int nt = 0; nt < NT; nt++) {
            int col = wn + nt * 8 + 2 * t;
            if (r0 < NN) {
                __half2 h = __floats2half2_rn(acc[mt][nt][0] * n0, acc[mt][nt][1] * n0);
                *(__half2*)(Yh + (size_t)r0 * BN + col) = h;
            }
            if (r1 < NN) {
                __half2 h = __floats2half2_rn(acc[mt][nt][2] * n1, acc[mt][nt][3] * n1);
                *(__half2*)(Yh + (size_t)r1 * BN + col) = h;
            }
        }
    }
    cudaTriggerProgrammaticLaunchCompletion();
}

// ---------------- Aggregation: one warp per node, unroll-8 uint2 gather ---------
// PDL: rowptr/norm/bias/first index batch (written in CSR phase) pre-sync;
// Yh gathers (fresh GEMM output) post-sync.
// MODE 0: leaky(o) -> half buffer   MODE 1: x=(x+leaky(o))/2 fp16 in place
// MODE 3: MODE 1 + unrounded fp32 mirror to out2
template <int MODE>
__global__ __launch_bounds__(128) void agg_kernel(const __half* __restrict__ Yh,
                                                  const float* __restrict__ bias,
                                                  __half* __restrict__ xbuf,
                                                  float* __restrict__ out2) {
    int gw = (blockIdx.x * 128 + threadIdx.x) >> 5;
    int lane = threadIdx.x & 31;
    int beg = 0, end = 0;
    float nm = 0.f;
    float4 b = make_float4(0.f, 0.f, 0.f, 0.f);
    const int* __restrict__ col = g_col;
    int s0p = 0;
    if (gw < NN) {
        beg = g_rowptr[gw];
        end = g_rowptr[gw + 1];
        nm = g_norm[gw];
        b = ((const float4*)bias)[lane];
        if (beg < end) s0p = col[beg];   // prefetch first index pre-sync
    }
    cudaGridDependencySynchronize();
    if (gw >= NN) return;
    (void)s0p;
    const uint2* Y4 = (const uint2*)Yh;
    uint2 sv = Y4[(size_t)gw * 32 + lane];
    float2 f0 = u2f2(sv.x), f1 = u2f2(sv.y);
    float4 acc = make_float4(f0.x, f0.y, f1.x, f1.y);
    int e = beg;
#define ACCV(vv) { float2 p_ = u2f2(vv.x), q_ = u2f2(vv.y); \
                   acc.x += p_.x; acc.y += p_.y; acc.z += q_.x; acc.w += q_.y; }
    for (; e + 7 < end; e += 8) {
        int c0 = col[e],     c1 = col[e + 1], c2 = col[e + 2], c3 = col[e + 3];
        int c4 = col[e + 4], c5 = col[e + 5], c6 = col[e + 6], c7 = col[e + 7];
        uint2 v0 = Y4[(size_t)c0 * 32 + lane];
        uint2 v1 = Y4[(size_t)c1 * 32 + lane];
        uint2 v2 = Y4[(size_t)c2 * 32 + lane];
        uint2 v3 = Y4[(size_t)c3 * 32 + lane];
        uint2 v4 = Y4[(size_t)c4 * 32 + lane];
        uint2 v5 = Y4[(size_t)c5 * 32 + lane];
        uint2 v6 = Y4[(size_t)c6 * 32 + lane];
        uint2 v7 = Y4[(size_t)c7 * 32 + lane];
        ACCV(v0) ACCV(v1) ACCV(v2) ACCV(v3)
        ACCV(v4) ACCV(v5) ACCV(v6) ACCV(v7)
    }
    for (; e + 1 < end; e += 2) {
        int c0 = col[e], c1 = col[e + 1];
        uint2 v0 = Y4[(size_t)c0 * 32 + lane];
        uint2 v1 = Y4[(size_t)c1 * 32 + lane];
        ACCV(v0) ACCV(v1)
    }
    if (e < end) {
        uint2 v = Y4[(size_t)col[e] * 32 + lane];
        ACCV(v)
    }
#undef ACCV
    float4 o = make_float4(acc.x * nm + b.x, acc.y * nm + b.y,
                           acc.z * nm + b.z, acc.w * nm + b.w);
    size_t idx = (size_t)gw * 32 + lane;
    float4 l4 = make_float4(lk(o.x), lk(o.y), lk(o.z), lk(o.w));
    float4 nv;
    if constexpr (MODE == 0) {
        nv = l4;
    } else {
        uint2 xr = ((const uint2*)xbuf)[idx];
        float2 x0 = u2f2(xr.x), x1 = u2f2(xr.y);
        nv = make_float4((x0.x + l4.x) * 0.5f, (x0.y + l4.y) * 0.5f,
                         (x1.x + l4.z) * 0.5f, (x1.y + l4.w) * 0.5f);
        if constexpr (MODE == 3) ((float4*)out2)[idx] = nv;
    }
    uint2 p;
    __half2 h01 = __floats2half2_rn(nv.x, nv.y);
    __half2 h23 = __floats2half2_rn(nv.z, nv.w);
    p.x = *reinterpret_cast<unsigned*>(&h01);
    p.y = *reinterpret_cast<unsigned*>(&h23);
    ((uint2*)xbuf)[idx] = p;
    cudaTriggerProgrammaticLaunchCompletion();
}

// ---------------- final aggregation (output conv, D=64, no activation) --------
__global__ __launch_bounds__(128) void agg64_kernel(const __half* __restrict__ Yh,
                                                    const float* __restrict__ bias,
                                                    float* __restrict__ outp) {
    int gw = (blockIdx.x * 128 + threadIdx.x) >> 5;
    int lane = threadIdx.x & 31;
    int beg = 0, end = 0;
    float nm = 0.f;
    float2 b = make_float2(0.f, 0.f);
    const int* __restrict__ col = g_col;
    if (gw < NN) {
        beg = g_rowptr[gw];
        end = g_rowptr[gw + 1];
        nm = g_norm[gw];
        b = ((const float2*)bias)[lane];
    }
    cudaGridDependencySynchronize();
    if (gw >= NN) return;
    const unsigned* Y2 = (const unsigned*)Yh;
    float2 acc = u2f2(Y2[(size_t)gw * 32 + lane]);
    int e = beg;
    for (; e + 7 < end; e += 8) {
        int s0 = col[e],     s1 = col[e + 1], s2 = col[e + 2], s3 = col[e + 3];
        int s4 = col[e + 4], s5 = col[e + 5], s6 = col[e + 6], s7 = col[e + 7];
        float2 v0 = u2f2(Y2[(size_t)s0 * 32 + lane]);
        float2 v1 = u2f2(Y2[(size_t)s1 * 32 + lane]);
        float2 v2 = u2f2(Y2[(size_t)s2 * 32 + lane]);
        float2 v3 = u2f2(Y2[(size_t)s3 * 32 + lane]);
        float2 v4 = u2f2(Y2[(size_t)s4 * 32 + lane]);
        float2 v5 = u2f2(Y2[(size_t)s5 * 32 + lane]);
        float2 v6 = u2f2(Y2[(size_t)s6 * 32 + lane]);
        float2 v7 = u2f2(Y2[(size_t)s7 * 32 + lane]);
        acc.x += ((v0.x + v1.x) + (v2.x + v3.x)) + ((v4.x + v5.x) + (v6.x + v7.x));
        acc.y += ((v0.y + v1.y) + (v2.y + v3.y)) + ((v4.y + v5.y) + (v6.y + v7.y));
    }
    for (; e < end; e++) {
        float2 v = u2f2(Y2[(size_t)col[e] * 32 + lane]);
        acc.x += v.x; acc.y += v.y;
    }
    ((float2*)outp)[(size_t)gw * 32 + lane] =
        make_float2(acc.x * nm + b.x, acc.y * nm + b.y);
}

// ---------------- PDL launch helper ----------------
template <typename F, typename... Args>
static void pdl_launch(F* f, int grid, int block, size_t smem, Args... args) {
    cudaLaunchConfig_t cfg = {};
    cudaLaunchAttribute at[1];
    at[0].id = cudaLaunchAttributeProgrammaticStreamSerialization;
    at[0].val.programmaticStreamSerializationAllowed = 1;
    cfg.gridDim = dim3(grid, 1, 1);
    cfg.blockDim = dim3(block, 1, 1);
    cfg.dynamicSmemBytes = smem;
    cfg.stream = 0;
    cfg.attrs = at;
    cfg.numAttrs = 1;
    cudaLaunchKernelEx(&cfg, f, args...);
}

// ---------------- launch ----------------
extern "C" void kernel_launch(void* const* d_in, const int* in_sizes, int n_in,
                              void* d_out, int out_size) {
    const float* inputs = (const float*)d_in[0];
    const int*   edges  = (const int*)d_in[1];
    const float* b_in   = (const float*)d_in[3];
    const float* b1     = (const float*)d_in[5];
    const float* b2     = (const float*)d_in[7];
    const float* b_out  = (const float*)d_in[9];
    float* out = (float*)d_out;

    const int* src = edges;
    const int* dst = edges + NE;

    void *pyh, *phh, *pxh, *pwh, *pwl, *pcnt;
    cudaGetSymbolAddress(&pyh, g_yh);
    cudaGetSymbolAddress(&phh, g_hh);
    cudaGetSymbolAddress(&pxh, g_xh);
    cudaGetSymbolAddress(&pwh, g_wh);
    cudaGetSymbolAddress(&pwl, g_wl);
    cudaGetSymbolAddress(&pcnt, g_cnt);
    __half* yh = (__half*)pyh;
    __half* hh = (__half*)phh;
    __half* xh = (__half*)pxh;
    __half* wh = (__half*)pwh;
    __half* wl = (__half*)pwl;

    // dynamic smem: 2 buffers of (A 128*40 + Bh BN*40 + Bl BN*40) halves
    const int SM128 = 2 * (128 * 40 + 2 * 128 * 40) * 2;  // 61440 B
    const int SM64  = 2 * (128 * 40 + 2 * 64 * 40) * 2;   // 40960 B
    cudaFuncSetAttribute(gemm_tc_kernel<128, float>,
                         cudaFuncAttributeMaxDynamicSharedMemorySize, SM128);
    cudaFuncSetAttribute(gemm_tc_kernel<128, __half>,
                         cudaFuncAttributeMaxDynamicSharedMemorySize, SM128);
    cudaFuncSetAttribute(gemm_tc_kernel<64, __half>,
                         cudaFuncAttributeMaxDynamicSharedMemorySize, SM64);

    const int GE = (NE + 255) / 256;
    const int GG = (NN + 127) / 128;       // gemm blocks
    const int GA = (NN * 32 + 127) / 128;  // agg blocks (warp/node, 128-thr blocks)
    const int GW = (NMAT * HD * HD + 255) / 256;
    const size_t WSTEP = (size_t)HD * HD;

    // weight split/transpose + CSR build
    pdl_launch(prep_w_kernel, GW, 256, 0,
               (const float*)d_in[2], (const float*)d_in[4],
               (const float*)d_in[6], (const float*)d_in[8]);
    cudaMemsetAsync(pcnt, 0, NN * sizeof(int));
    pdl_launch(count_kernel, GE, 256, 0, dst);
    pdl_launch(scan_blocks_kernel, NSB, 1024, 0);
    pdl_launch(scan_fix_kernel, NSB, 1024, 0);
    pdl_launch(fill_kernel, GE, 256, 0, src, dst);

    // input conv
    pdl_launch(gemm_tc_kernel<128, float>, GG, 256, SM128,
               inputs, (const __half*)wh, (const __half*)wl, yh);
    pdl_launch(agg_kernel<0>, GA, 128, 0,
               (const __half*)yh, b_in, xh, (float*)nullptr);

    // 6 residual blocks; last one mirrors fp32 x into d_out's second half
    for (int i = 0; i < 6; i++) {
        pdl_launch(gemm_tc_kernel<128, __half>, GG, 256, SM128,
                   (const __half*)xh, (const __half*)(wh + (size_t)(1 + i) * WSTEP),
                   (const __half*)(wl + (size_t)(1 + i) * WSTEP), yh);
        pdl_launch(agg_kernel<0>, GA, 128, 0,
                   (const __half*)yh, b1 + (size_t)i * HD, hh, (float*)nullptr);
        pdl_launch(gemm_tc_kernel<128, __half>, GG, 256, SM128,
                   (const __half*)hh, (const __half*)(wh + (size_t)(7 + i) * WSTEP),
                   (const __half*)(wl + (size_t)(7 + i) * WSTEP), yh);
        if (i < 5)
            pdl_launch(agg_kernel<1>, GA, 128, 0,
                       (const __half*)yh, b2 + (size_t)i * HD, xh, (float*)nullptr);
        else
            pdl_launch(agg_kernel<3>, GA, 128, 0,
                       (const __half*)yh, b2 + (size_t)i * HD, xh,
                       out + (size_t)NN * 64);
    }

    // output conv (no activation), writes first N*64 floats of d_out
    pdl_launch(gemm_tc_kernel<64, __half>, GG, 256, SM64,
               (const __half*)xh, (const __half*)(wh + (size_t)13 * WSTEP),
               (const __half*)(wl + (size_t)13 * WSTEP), yh);
    pdl_launch(agg64_kernel, GA, 128, 0,
               (const __half*)yh, b_out, out);
}

// round 14
// speedup vs baseline: 1.2015x; 1.0234x over previous
#include <cuda_runtime.h>
#include <cuda_fp16.h>
#include <cuda_bf16.h>

#define NN 50000
#define NE 800000
#define HD 128
#define NMAT 14
#define NSB 49   // scan blocks: ceil(50000/1024)

// ---------------- device scratch (no allocations allowed) ----------------
__device__ __half  g_yh[(size_t)NN * HD];   // fp16 messages (GEMM output, norm-scaled)
__device__ __half  g_hh[(size_t)NN * HD];   // fp16 block intermediate h
__device__ __half  g_xh[(size_t)NN * HD];   // fp16 running x master
__device__ float   g_norm[NN];
__device__ int     g_rowptr[NN + 1];
__device__ int     g_cnt[NN];
__device__ int     g_off[NN];
__device__ int     g_col[NE];
__device__ int     g_bsum[NSB];             // raw per-block totals
__device__ __half  g_wh[(size_t)NMAT * HD * HD];  // weights, n-major, fp16 hi
__device__ __half  g_wl[(size_t)NMAT * HD * HD];  // fp16 lo residual

__device__ __forceinline__ float lk(float v) { return v >= 0.f ? v : 0.01f * v; }

__device__ __forceinline__ float2 u2f2(unsigned u) {
    __half2 h = *reinterpret_cast<__half2*>(&u);
    return __half22float2(h);
}

// ---------------- CSR build ----------------
__global__ void count_kernel(const int* __restrict__ dst) {
    int e = blockIdx.x * blockDim.x + threadIdx.x;
    int d = (e < NE) ? dst[e] : 0;          // harness input: safe pre-sync
    cudaGridDependencySynchronize();        // wait for memset of g_cnt
    cudaTriggerProgrammaticLaunchCompletion();
    if (e < NE) atomicAdd(&g_cnt[d], 1);
}

__global__ __launch_bounds__(1024) void scan_blocks_kernel() {
    __shared__ int ws[32];
    int tid = threadIdx.x, lane = tid & 31, wid = tid >> 5;
    int i = blockIdx.x * 1024 + tid;
    cudaGridDependencySynchronize();        // g_cnt dependent
    int v = (i < NN) ? g_cnt[i] : 0;
    int x = v;
#pragma unroll
    for (int d = 1; d < 32; d <<= 1) {
        int t = __shfl_up_sync(0xffffffffu, x, d);
        if (lane >= d) x += t;
    }
    if (lane == 31) ws[wid] = x;
    __syncthreads();
    if (wid == 0) {
        int s = ws[lane];
#pragma unroll
        for (int d = 1; d < 32; d <<= 1) {
            int t = __shfl_up_sync(0xffffffffu, s, d);
            if (lane >= d) s += t;
        }
        ws[lane] = s;
    }
    __syncthreads();
    int off = wid ? ws[wid - 1] : 0;
    if (i < NN) g_rowptr[i] = off + x - v;
    if (tid == 1023) g_bsum[blockIdx.x] = off + x;
    cudaTriggerProgrammaticLaunchCompletion();
}

__global__ __launch_bounds__(1024) void scan_fix_kernel() {
    __shared__ int s_off;
    int tid = threadIdx.x;
    cudaGridDependencySynchronize();        // rowptr/bsum dependent
    if (tid < 32) {
        int b = blockIdx.x;
        int t0 = (tid < NSB && tid < b) ? g_bsum[tid] : 0;
        int t1 = (tid + 32 < NSB && tid + 32 < b) ? g_bsum[tid + 32] : 0;
        int s = t0 + t1;
#pragma unroll
        for (int d = 16; d >= 1; d >>= 1) s += __shfl_xor_sync(0xffffffffu, s, d);
        if (tid == 0) s_off = s;
    }
    __syncthreads();
    int i = blockIdx.x * 1024 + tid;
    if (i < NN) {
        int r = g_rowptr[i] + s_off;
        g_rowptr[i] = r;
        g_off[i] = r;
        g_norm[i] = rsqrtf(1.0f + (float)g_cnt[i]);
    }
    if (blockIdx.x == 0 && tid == 0) g_rowptr[NN] = NE;
    cudaTriggerProgrammaticLaunchCompletion();
}

__global__ void fill_kernel(const int* __restrict__ src, const int* __restrict__ dst) {
    int e = blockIdx.x * blockDim.x + threadIdx.x;
    int s = 0, d = 0;
    if (e < NE) { s = src[e]; d = dst[e]; }  // harness inputs: safe pre-sync
    cudaGridDependencySynchronize();         // g_off dependent
    if (e < NE) {
        int p = atomicAdd(&g_off[d], 1);
        g_col[p] = s;
    }
    cudaTriggerProgrammaticLaunchCompletion();
}

// ---------------- weight prep: transpose to n-major, split fp32 -> fp16 hi/lo ----
__global__ void prep_w_kernel(const float* __restrict__ w_in, const float* __restrict__ w1,
                              const float* __restrict__ w2, const float* __restrict__ w_out) {
    int idx = blockIdx.x * blockDim.x + threadIdx.x;
    if (idx >= NMAT * HD * HD) return;
    int mat = idx >> 14;
    int rem = idx & 16383;
    int n = rem >> 7, k = rem & 127;
    float v;
    if (mat == 0)       v = w_in[k * HD + n];
    else if (mat <= 6)  v = w1[(size_t)(mat - 1) * HD * HD + k * HD + n];
    else if (mat <= 12) v = w2[(size_t)(mat - 7) * HD * HD + k * HD + n];
    else                v = (n < 64) ? w_out[k * 64 + n] : 0.f;
    cudaGridDependencySynchronize();   // guard vs prior graph replay's readers
    __half hi = __float2half_rn(v);
    __half lo = __float2half_rn(v - __half2float(hi));
    g_wh[idx] = hi;
    g_wl[idx] = lo;
    cudaTriggerProgrammaticLaunchCompletion();
}

// ---------------- fp16 MMA helper (fp32 accumulate) ----------------
__device__ __forceinline__ void mma_f16(float* c, unsigned a0, unsigned a1, unsigned a2,
                                        unsigned a3, unsigned b0, unsigned b1) {
    asm volatile(
        "mma.sync.aligned.m16n8k16.row.col.f32.f16.f16.f32 "
        "{%0,%1,%2,%3}, {%4,%5,%6,%7}, {%8,%9}, {%0,%1,%2,%3};"
        : "+f"(c[0]), "+f"(c[1]), "+f"(c[2]), "+f"(c[3])
        : "r"(a0), "r"(a1), "r"(a2), "r"(a3), "r"(b0), "r"(b1));
}

__device__ __forceinline__ void ldsm_x4(unsigned& d0, unsigned& d1, unsigned& d2,
                                        unsigned& d3, unsigned addr) {
    asm volatile("ldmatrix.sync.aligned.m8n8.x4.shared.b16 {%0,%1,%2,%3}, [%4];"
                 : "=r"(d0), "=r"(d1), "=r"(d2), "=r"(d3) : "r"(addr));
}

// ---------------- tensor-core GEMM, double-buffered smem, LDSM fragments -------
// Y = half((A@W)*norm), K=128. A fp32->fp16 or fp16; W split fp16 hi/lo.
// PDL: B tile 0 loads pre-sync; A (fresh agg output) loads post-sync.
template <int BN, typename AT>
__global__ __launch_bounds__(256) void gemm_tc_kernel(const AT* __restrict__ A,
                                                      const __half* __restrict__ Wh,
                                                      const __half* __restrict__ Wl,
                                                      __half* __restrict__ Yh) {
    constexpr int BM = 128, BK = 32, K = 128;
    constexpr int WN = BN / 4;   // 32 or 16
    constexpr int NT = WN / 8;   // 4 or 2
    constexpr int NJ = NT / 2;   // ldmatrix.x4 groups per B operand: 2 or 1
    constexpr int SA = 40;
    constexpr int ASZ = BM * SA;       // per-buffer A halves
    constexpr int BSZ = BN * SA;       // per-buffer B halves
    extern __shared__ __half smem[];
    __half* sA  = smem;                // 2 * ASZ
    __half* sBh = smem + 2 * ASZ;      // 2 * BSZ
    __half* sBl = sBh + 2 * BSZ;       // 2 * BSZ

    const int tid = threadIdx.x, lane = tid & 31, wid = tid >> 5;
    const int g = lane >> 2, t = lane & 3;
    const int mat = lane >> 3, mr = lane & 7;   // ldmatrix role
    const int wm = (wid & 1) * 64, wn = (wid >> 1) * WN;
    const int m0 = blockIdx.x * BM;

    const unsigned sA_u  = (unsigned)__cvta_generic_to_shared(sA);
    const unsigned sBh_u = (unsigned)__cvta_generic_to_shared(sBh);
    const unsigned sBl_u = (unsigned)__cvta_generic_to_shared(sBl);

    // ldmatrix relative half-offsets (within one buffer)
    unsigned aRel[4];
#pragma unroll
    for (int mt = 0; mt < 4; mt++)
        aRel[mt] = (unsigned)((wm + mt * 16 + (mat & 1) * 8 + mr) * SA + (mat >> 1) * 8);
    unsigned bRel[NJ];
#pragma unroll
    for (int j = 0; j < NJ; j++)
        bRel[j] = (unsigned)((wn + (j * 2 + (mat >> 1)) * 8 + mr) * SA + (mat & 1) * 8);

    float acc[4][NT][4];
#pragma unroll
    for (int i = 0; i < 4; i++)
#pragma unroll
        for (int j = 0; j < NT; j++)
#pragma unroll
            for (int q = 0; q < 4; q++) acc[i][j][q] = 0.f;

    float4 vaf[4];
    uint2  vah[4];
    uint4 vbh[2], vbl[2];

    auto loadA = [&](int k0) {
#pragma unroll
        for (int l = 0; l < 4; l++) {
            int idx = tid + l * 256, r = idx >> 3, c = idx & 7;
            if constexpr (sizeof(AT) == 4) {
                vaf[l] = make_float4(0.f, 0.f, 0.f, 0.f);
                if (m0 + r < NN)
                    vaf[l] = *(const float4*)((const float*)A + (size_t)(m0 + r) * K + k0 + c * 4);
            } else {
                vah[l] = make_uint2(0u, 0u);
                if (m0 + r < NN)
                    vah[l] = *(const uint2*)((const __half*)A + (size_t)(m0 + r) * K + k0 + c * 4);
            }
        }
    };
    auto loadB = [&](int k0) {
        if constexpr (BN == 128) {
            int n = tid >> 1, kh = (tid & 1) * 16;
            vbh[0] = *(const uint4*)&Wh[(size_t)n * K + k0 + kh];
            vbh[1] = *(const uint4*)&Wh[(size_t)n * K + k0 + kh + 8];
            vbl[0] = *(const uint4*)&Wl[(size_t)n * K + k0 + kh];
            vbl[1] = *(const uint4*)&Wl[(size_t)n * K + k0 + kh + 8];
        } else {
            int n = tid >> 2, kh = (tid & 3) * 8;
            vbh[0] = *(const uint4*)&Wh[(size_t)n * K + k0 + kh];
            vbl[0] = *(const uint4*)&Wl[(size_t)n * K + k0 + kh];
        }
    };
    auto storeTiles = [&](int buf) {
        __half* dA  = sA  + buf * ASZ;
        __half* dBh = sBh + buf * BSZ;
        __half* dBl = sBl + buf * BSZ;
#pragma unroll
        for (int l = 0; l < 4; l++) {
            int idx = tid + l * 256, r = idx >> 3, c = idx & 7;
            if constexpr (sizeof(AT) == 4) {
                float4 v = vaf[l];
                __half2 h01 = __floats2half2_rn(v.x, v.y);
                __half2 h23 = __floats2half2_rn(v.z, v.w);
                *(__half2*)&dA[r * SA + c * 4]     = h01;
                *(__half2*)&dA[r * SA + c * 4 + 2] = h23;
            } else {
                *(uint2*)&dA[r * SA + c * 4] = vah[l];
            }
        }
        if constexpr (BN == 128) {
            int n = tid >> 1, kh = (tid & 1) * 16;
            *(uint4*)&dBh[n * SA + kh]     = vbh[0];
            *(uint4*)&dBh[n * SA + kh + 8] = vbh[1];
            *(uint4*)&dBl[n * SA + kh]     = vbl[0];
            *(uint4*)&dBl[n * SA + kh + 8] = vbl[1];
        } else {
            int n = tid >> 2, kh = (tid & 3) * 8;
            *(uint4*)&dBh[n * SA + kh] = vbh[0];
            *(uint4*)&dBl[n * SA + kh] = vbl[0];
        }
    };

    loadB(0);                         // independent prologue (weights)
    cudaGridDependencySynchronize();  // wait for A producer
    loadA(0);
    storeTiles(0);
    __syncthreads();
#pragma unroll
    for (int s = 0; s < 4; s++) {
        if (s < 3) { loadA((s + 1) * BK); loadB((s + 1) * BK); }
        const int buf = s & 1;
        const unsigned cA_u  = sA_u  + (unsigned)(buf * ASZ) * 2u;
        const unsigned cBh_u = sBh_u + (unsigned)(buf * BSZ) * 2u;
        const unsigned cBl_u = sBl_u + (unsigned)(buf * BSZ) * 2u;
#pragma unroll
        for (int kk = 0; kk < BK; kk += 16) {
            unsigned bh[NT][2], bl[NT][2];
#pragma unroll
            for (int j = 0; j < NJ; j++) {
                unsigned off = (bRel[j] + (unsigned)kk) * 2u;
                ldsm_x4(bh[j * 2][0], bh[j * 2][1], bh[j * 2 + 1][0], bh[j * 2 + 1][1],
                        cBh_u + off);
                ldsm_x4(bl[j * 2][0], bl[j * 2][1], bl[j * 2 + 1][0], bl[j * 2 + 1][1],
                        cBl_u + off);
            }
#pragma unroll
            for (int mt = 0; mt < 4; mt++) {
                unsigned a0, a1, a2, a3;
                ldsm_x4(a0, a1, a2, a3, cA_u + (aRel[mt] + (unsigned)kk) * 2u);
#pragma unroll
                for (int nt = 0; nt < NT; nt++) {
                    mma_f16(acc[mt][nt], a0, a1, a2, a3, bh[nt][0], bh[nt][1]);
                    mma_f16(acc[mt][nt], a0, a1, a2, a3, bl[nt][0], bl[nt][1]);
                }
            }
        }
        if (s < 3) {
            storeTiles(1 - buf);
            __syncthreads();
        }
    }

#pragma unroll
    for (int mt = 0; mt < 4; mt++) {
        int r0 = m0 + wm + mt * 16 + g, r1 = r0 + 8;
        float n0 = (r0 < NN) ? g_norm[r0] : 0.f;
        float n1 = (r1 < NN) ? g_norm[r1] : 0.f;
#pragma unroll
        for (int nt = 0; nt < NT; nt++) {
            int col = wn + nt * 8 + 2 * t;
            if (r0 < NN) {
                __half2 h = __floats2half2_rn(acc[mt][nt][0] * n0, acc[mt][nt][1] * n0);
                *(__half2*)(Yh + (size_t)r0 * BN + col) = h;
            }
            if (r1 < NN) {
                __half2 h = __floats2half2_rn(acc[mt][nt][2] * n1, acc[mt][nt][3] * n1);
                *(__half2*)(Yh + (size_t)r1 * BN + col) = h;
            }
        }
    }
    cudaTriggerProgrammaticLaunchCompletion();
}

// ---------------- Aggregation: one warp per node, unroll-8 uint2 gather ---------
// PDL: rowptr/norm/bias pre-sync; Yh gathers (fresh GEMM output) post-sync.
// MODE 0: leaky(o) -> half buffer   MODE 1: x=(x+leaky(o))/2 fp16 in place
// MODE 3: MODE 1 + unrounded fp32 mirror to out2
template <int MODE>
__global__ __launch_bounds__(128) void agg_kernel(const __half* __restrict__ Yh,
                                                  const float* __restrict__ bias,
                                                  __half* __restrict__ xbuf,
                                                  float* __restrict__ out2) {
    int gw = (blockIdx.x * 128 + threadIdx.x) >> 5;
    int lane = threadIdx.x & 31;
    int beg = 0, end = 0;
    float nm = 0.f;
    float4 b = make_float4(0.f, 0.f, 0.f, 0.f);
    const int* __restrict__ col = g_col;
    int s0p = 0;
    if (gw < NN) {
        beg = g_rowptr[gw];
        end = g_rowptr[gw + 1];
        nm = g_norm[gw];
        b = ((const float4*)bias)[lane];
        if (beg < end) s0p = col[beg];   // prefetch first index pre-sync
    }
    cudaGridDependencySynchronize();
    if (gw >= NN) return;
    (void)s0p;
    const uint2* Y4 = (const uint2*)Yh;
    uint2 sv = Y4[(size_t)gw * 32 + lane];
    float2 f0 = u2f2(sv.x), f1 = u2f2(sv.y);
    float4 acc = make_float4(f0.x, f0.y, f1.x, f1.y);
    int e = beg;
#define ACCV(vv) { float2 p_ = u2f2(vv.x), q_ = u2f2(vv.y); \
                   acc.x += p_.x; acc.y += p_.y; acc.z += q_.x; acc.w += q_.y; }
    for (; e + 7 < end; e += 8) {
        int c0 = col[e],     c1 = col[e + 1], c2 = col[e + 2], c3 = col[e + 3];
        int c4 = col[e + 4], c5 = col[e + 5], c6 = col[e + 6], c7 = col[e + 7];
        uint2 v0 = Y4[(size_t)c0 * 32 + lane];
        uint2 v1 = Y4[(size_t)c1 * 32 + lane];
        uint2 v2 = Y4[(size_t)c2 * 32 + lane];
        uint2 v3 = Y4[(size_t)c3 * 32 + lane];
        uint2 v4 = Y4[(size_t)c4 * 32 + lane];
        uint2 v5 = Y4[(size_t)c5 * 32 + lane];
        uint2 v6 = Y4[(size_t)c6 * 32 + lane];
        uint2 v7 = Y4[(size_t)c7 * 32 + lane];
        ACCV(v0) ACCV(v1) ACCV(v2) ACCV(v3)
        ACCV(v4) ACCV(v5) ACCV(v6) ACCV(v7)
    }
    for (; e + 1 < end; e += 2) {
        int c0 = col[e], c1 = col[e + 1];
        uint2 v0 = Y4[(size_t)c0 * 32 + lane];
        uint2 v1 = Y4[(size_t)c1 * 32 + lane];
        ACCV(v0) ACCV(v1)
    }
    if (e < end) {
        uint2 v = Y4[(size_t)col[e] * 32 + lane];
        ACCV(v)
    }
#undef ACCV
    float4 o = make_float4(acc.x * nm + b.x, acc.y * nm + b.y,
                           acc.z * nm + b.z, acc.w * nm + b.w);
    size_t idx = (size_t)gw * 32 + lane;
    float4 l4 = make_float4(lk(o.x), lk(o.y), lk(o.z), lk(o.w));
    float4 nv;
    if constexpr (MODE == 0) {
        nv = l4;
    } else {
        uint2 xr = ((const uint2*)xbuf)[idx];
        float2 x0 = u2f2(xr.x), x1 = u2f2(xr.y);
        nv = make_float4((x0.x + l4.x) * 0.5f, (x0.y + l4.y) * 0.5f,
                         (x1.x + l4.z) * 0.5f, (x1.y + l4.w) * 0.5f);
        if constexpr (MODE == 3) ((float4*)out2)[idx] = nv;
    }
    uint2 p;
    __half2 h01 = __floats2half2_rn(nv.x, nv.y);
    __half2 h23 = __floats2half2_rn(nv.z, nv.w);
    p.x = *reinterpret_cast<unsigned*>(&h01);
    p.y = *reinterpret_cast<unsigned*>(&h23);
    ((uint2*)xbuf)[idx] = p;
    cudaTriggerProgrammaticLaunchCompletion();
}

// ---------------- final aggregation (output conv, D=64, no activation) --------
__global__ __launch_bounds__(128) void agg64_kernel(const __half* __restrict__ Yh,
                                                    const float* __restrict__ bias,
                                                    float* __restrict__ outp) {
    int gw = (blockIdx.x * 128 + threadIdx.x) >> 5;
    int lane = threadIdx.x & 31;
    int beg = 0, end = 0;
    float nm = 0.f;
    float2 b = make_float2(0.f, 0.f);
    const int* __restrict__ col = g_col;
    if (gw < NN) {
        beg = g_rowptr[gw];
        end = g_rowptr[gw + 1];
        nm = g_norm[gw];
        b = ((const float2*)bias)[lane];
    }
    cudaGridDependencySynchronize();
    if (gw >= NN) return;
    const unsigned* Y2 = (const unsigned*)Yh;
    float2 acc = u2f2(Y2[(size_t)gw * 32 + lane]);
    int e = beg;
    for (; e + 7 < end; e += 8) {
        int s0 = col[e],     s1 = col[e + 1], s2 = col[e + 2], s3 = col[e + 3];
        int s4 = col[e + 4], s5 = col[e + 5], s6 = col[e + 6], s7 = col[e + 7];
        float2 v0 = u2f2(Y2[(size_t)s0 * 32 + lane]);
        float2 v1 = u2f2(Y2[(size_t)s1 * 32 + lane]);
        float2 v2 = u2f2(Y2[(size_t)s2 * 32 + lane]);
        float2 v3 = u2f2(Y2[(size_t)s3 * 32 + lane]);
        float2 v4 = u2f2(Y2[(size_t)s4 * 32 + lane]);
        float2 v5 = u2f2(Y2[(size_t)s5 * 32 + lane]);
        float2 v6 = u2f2(Y2[(size_t)s6 * 32 + lane]);
        float2 v7 = u2f2(Y2[(size_t)s7 * 32 + lane]);
        acc.x += ((v0.x + v1.x) + (v2.x + v3.x)) + ((v4.x + v5.x) + (v6.x + v7.x));
        acc.y += ((v0.y + v1.y) + (v2.y + v3.y)) + ((v4.y + v5.y) + (v6.y + v7.y));
    }
    for (; e < end; e++) {
        float2 v = u2f2(Y2[(size_t)col[e] * 32 + lane]);
        acc.x += v.x; acc.y += v.y;
    }
    ((float2*)outp)[(size_t)gw * 32 + lane] =
        make_float2(acc.x * nm + b.x, acc.y * nm + b.y);
}

// ---------------- PDL launch helper ----------------
template <typename F, typename... Args>
static void pdl_launch(F* f, int grid, int block, size_t smem, Args... args) {
    cudaLaunchConfig_t cfg = {};
    cudaLaunchAttribute at[1];
    at[0].id = cudaLaunchAttributeProgrammaticStreamSerialization;
    at[0].val.programmaticStreamSerializationAllowed = 1;
    cfg.gridDim = dim3(grid, 1, 1);
    cfg.blockDim = dim3(block, 1, 1);
    cfg.dynamicSmemBytes = smem;
    cfg.stream = 0;
    cfg.attrs = at;
    cfg.numAttrs = 1;
    cudaLaunchKernelEx(&cfg, f, args...);
}

// ---------------- launch ----------------
extern "C" void kernel_launch(void* const* d_in, const int* in_sizes, int n_in,
                              void* d_out, int out_size) {
    const float* inputs = (const float*)d_in[0];
    const int*   edges  = (const int*)d_in[1];
    const float* b_in   = (const float*)d_in[3];
    const float* b1     = (const float*)d_in[5];
    const float* b2     = (const float*)d_in[7];
    const float* b_out  = (const float*)d_in[9];
    float* out = (float*)d_out;

    const int* src = edges;
    const int* dst = edges + NE;

    void *pyh, *phh, *pxh, *pwh, *pwl, *pcnt;
    cudaGetSymbolAddress(&pyh, g_yh);
    cudaGetSymbolAddress(&phh, g_hh);
    cudaGetSymbolAddress(&pxh, g_xh);
    cudaGetSymbolAddress(&pwh, g_wh);
    cudaGetSymbolAddress(&pwl, g_wl);
    cudaGetSymbolAddress(&pcnt, g_cnt);
    __half* yh = (__half*)pyh;
    __half* hh = (__half*)phh;
    __half* xh = (__half*)pxh;
    __half* wh = (__half*)pwh;
    __half* wl = (__half*)pwl;

    // dynamic smem: 2 buffers of (A 128*40 + Bh BN*40 + Bl BN*40) halves
    const int SM128 = 2 * (128 * 40 + 2 * 128 * 40) * 2;  // 61440 B
    const int SM64  = 2 * (128 * 40 + 2 * 64 * 40) * 2;   // 40960 B
    cudaFuncSetAttribute(gemm_tc_kernel<128, float>,
                         cudaFuncAttributeMaxDynamicSharedMemorySize, SM128);
    cudaFuncSetAttribute(gemm_tc_kernel<128, __half>,
                         cudaFuncAttributeMaxDynamicSharedMemorySize, SM128);
    cudaFuncSetAttribute(gemm_tc_kernel<64, __half>,
                         cudaFuncAttributeMaxDynamicSharedMemorySize, SM64);

    const int GE = (NE + 255) / 256;
    const int GG = (NN + 127) / 128;       // gemm blocks
    const int GA = (NN * 32 + 127) / 128;  // agg blocks (warp/node, 128-thr blocks)
    const int GW = (NMAT * HD * HD + 255) / 256;
    const size_t WSTEP = (size_t)HD * HD;

    // weight split/transpose + CSR build
    pdl_launch(prep_w_kernel, GW, 256, 0,
               (const float*)d_in[2], (const float*)d_in[4],
               (const float*)d_in[6], (const float*)d_in[8]);
    cudaMemsetAsync(pcnt, 0, NN * sizeof(int));
    pdl_launch(count_kernel, GE, 256, 0, dst);
    pdl_launch(scan_blocks_kernel, NSB, 1024, 0);
    pdl_launch(scan_fix_kernel, NSB, 1024, 0);
    pdl_launch(fill_kernel, GE, 256, 0, src, dst);

    // input conv
    pdl_launch(gemm_tc_kernel<128, float>, GG, 256, SM128,
               inputs, (const __half*)wh, (const __half*)wl, yh);
    pdl_launch(agg_kernel<0>, GA, 128, 0,
               (const __half*)yh, b_in, xh, (float*)nullptr);

    // 6 residual blocks; last one mirrors fp32 x into d_out's second half
    for (int i = 0; i < 6; i++) {
        pdl_launch(gemm_tc_kernel<128, __half>, GG, 256, SM128,
                   (const __half*)xh, (const __half*)(wh + (size_t)(1 + i) * WSTEP),
                   (const __half*)(wl + (size_t)(1 + i) * WSTEP), yh);
        pdl_launch(agg_kernel<0>, GA, 128, 0,
                   (const __half*)yh, b1 + (size_t)i * HD, hh, (float*)nullptr);
        pdl_launch(gemm_tc_kernel<128, __half>, GG, 256, SM128,
                   (const __half*)hh, (const __half*)(wh + (size_t)(7 + i) * WSTEP),
                   (const __half*)(wl + (size_t)(7 + i) * WSTEP), yh);
        if (i < 5)
            pdl_launch(agg_kernel<1>, GA, 128, 0,
                       (const __half*)yh, b2 + (size_t)i * HD, xh, (float*)nullptr);
        else
            pdl_launch(agg_kernel<3>, GA, 128, 0,
                       (const __half*)yh, b2 + (size_t)i * HD, xh,
                       out + (size_t)NN * 64);
    }

    // output conv (no activation), writes first N*64 floats of d_out
    pdl_launch(gemm_tc_kernel<64, __half>, GG, 256, SM64,
               (const __half*)xh, (const __half*)(wh + (size_t)13 * WSTEP),
               (const __half*)(wl + (size_t)13 * WSTEP), yh);
    pdl_launch(agg64_kernel, GA, 128, 0,
               (const __half*)yh, b_out, out);
}

// round 16
// speedup vs baseline: 1.2093x; 1.0065x over previous
#include <cuda_runtime.h>
#include <cuda_fp16.h>
#include <cuda_bf16.h>

#define NN 50000
#define NE 800000
#define HD 128
#define NMAT 14
#define NSB 49   // scan blocks: ceil(50000/1024)

// ---------------- device scratch (no allocations allowed) ----------------
__device__ __half  g_yh[(size_t)NN * HD];   // fp16 messages (GEMM output, norm-scaled)
__device__ __half  g_hh[(size_t)NN * HD];   // fp16 block intermediate h
__device__ __half  g_xh[(size_t)NN * HD];   // fp16 running x master
__device__ float   g_norm[NN];
__device__ int     g_rowptr[NN + 1];
__device__ int     g_cnt[NN];
__device__ int     g_off[NN];
__device__ int     g_col[NE];
__device__ int     g_bsum[NSB];             // raw per-block totals
__device__ __half  g_wh[(size_t)NMAT * HD * HD];  // weights, n-major, fp16 hi
__device__ __half  g_wl[(size_t)NMAT * HD * HD];  // fp16 lo residual

__device__ __forceinline__ float lk(float v) { return v >= 0.f ? v : 0.01f * v; }

__device__ __forceinline__ float2 u2f2(unsigned u) {
    __half2 h = *reinterpret_cast<__half2*>(&u);
    return __half22float2(h);
}

// ---------------- CSR build ----------------
__global__ void count_kernel(const int* __restrict__ dst) {
    int e = blockIdx.x * blockDim.x + threadIdx.x;
    int d = (e < NE) ? dst[e] : 0;          // harness input: safe pre-sync
    cudaGridDependencySynchronize();        // wait for g_cnt zeroing (in prep_w)
    cudaTriggerProgrammaticLaunchCompletion();
    if (e < NE) atomicAdd(&g_cnt[d], 1);
}

__global__ __launch_bounds__(1024) void scan_blocks_kernel() {
    __shared__ int ws[32];
    int tid = threadIdx.x, lane = tid & 31, wid = tid >> 5;
    int i = blockIdx.x * 1024 + tid;
    cudaGridDependencySynchronize();        // g_cnt dependent
    int v = (i < NN) ? g_cnt[i] : 0;
    int x = v;
#pragma unroll
    for (int d = 1; d < 32; d <<= 1) {
        int t = __shfl_up_sync(0xffffffffu, x, d);
        if (lane >= d) x += t;
    }
    if (lane == 31) ws[wid] = x;
    __syncthreads();
    if (wid == 0) {
        int s = ws[lane];
#pragma unroll
        for (int d = 1; d < 32; d <<= 1) {
            int t = __shfl_up_sync(0xffffffffu, s, d);
            if (lane >= d) s += t;
        }
        ws[lane] = s;
    }
    __syncthreads();
    int off = wid ? ws[wid - 1] : 0;
    if (i < NN) g_rowptr[i] = off + x - v;
    if (tid == 1023) g_bsum[blockIdx.x] = off + x;
    cudaTriggerProgrammaticLaunchCompletion();
}

__global__ __launch_bounds__(1024) void scan_fix_kernel() {
    __shared__ int s_off;
    int tid = threadIdx.x;
    cudaGridDependencySynchronize();        // rowptr/bsum dependent
    if (tid < 32) {
        int b = blockIdx.x;
        int t0 = (tid < NSB && tid < b) ? g_bsum[tid] : 0;
        int t1 = (tid + 32 < NSB && tid + 32 < b) ? g_bsum[tid + 32] : 0;
        int s = t0 + t1;
#pragma unroll
        for (int d = 16; d >= 1; d >>= 1) s += __shfl_xor_sync(0xffffffffu, s, d);
        if (tid == 0) s_off = s;
    }
    __syncthreads();
    int i = blockIdx.x * 1024 + tid;
    if (i < NN) {
        int r = g_rowptr[i] + s_off;
        g_rowptr[i] = r;
        g_off[i] = r;
        g_norm[i] = rsqrtf(1.0f + (float)g_cnt[i]);
    }
    if (blockIdx.x == 0 && tid == 0) g_rowptr[NN] = NE;
    cudaTriggerProgrammaticLaunchCompletion();
}

__global__ void fill_kernel(const int* __restrict__ src, const int* __restrict__ dst) {
    int e = blockIdx.x * blockDim.x + threadIdx.x;
    int s = 0, d = 0;
    if (e < NE) { s = src[e]; d = dst[e]; }  // harness inputs: safe pre-sync
    cudaGridDependencySynchronize();         // g_off dependent
    if (e < NE) {
        int p = atomicAdd(&g_off[d], 1);
        g_col[p] = s;
    }
    cudaTriggerProgrammaticLaunchCompletion();
}

// ---------------- weight prep + g_cnt zeroing ----------------
__global__ void prep_w_kernel(const float* __restrict__ w_in, const float* __restrict__ w1,
                              const float* __restrict__ w2, const float* __restrict__ w_out) {
    int idx = blockIdx.x * blockDim.x + threadIdx.x;
    if (idx >= NMAT * HD * HD) return;
    int mat = idx >> 14;
    int rem = idx & 16383;
    int n = rem >> 7, k = rem & 127;
    float v;
    if (mat == 0)       v = w_in[k * HD + n];
    else if (mat <= 6)  v = w1[(size_t)(mat - 1) * HD * HD + k * HD + n];
    else if (mat <= 12) v = w2[(size_t)(mat - 7) * HD * HD + k * HD + n];
    else                v = (n < 64) ? w_out[k * 64 + n] : 0.f;
    cudaGridDependencySynchronize();   // guard vs prior graph replay's readers
    if (idx < NN) g_cnt[idx] = 0;      // fused zeroing (replaces memset launch)
    __half hi = __float2half_rn(v);
    __half lo = __float2half_rn(v - __half2float(hi));
    g_wh[idx] = hi;
    g_wl[idx] = lo;
    cudaTriggerProgrammaticLaunchCompletion();
}

// ---------------- fp16 MMA helper (fp32 accumulate) ----------------
__device__ __forceinline__ void mma_f16(float* c, unsigned a0, unsigned a1, unsigned a2,
                                        unsigned a3, unsigned b0, unsigned b1) {
    asm volatile(
        "mma.sync.aligned.m16n8k16.row.col.f32.f16.f16.f32 "
        "{%0,%1,%2,%3}, {%4,%5,%6,%7}, {%8,%9}, {%0,%1,%2,%3};"
        : "+f"(c[0]), "+f"(c[1]), "+f"(c[2]), "+f"(c[3])
        : "r"(a0), "r"(a1), "r"(a2), "r"(a3), "r"(b0), "r"(b1));
}

__device__ __forceinline__ void ldsm_x4(unsigned& d0, unsigned& d1, unsigned& d2,
                                        unsigned& d3, unsigned addr) {
    asm volatile("ldmatrix.sync.aligned.m8n8.x4.shared.b16 {%0,%1,%2,%3}, [%4];"
                 : "=r"(d0), "=r"(d1), "=r"(d2), "=r"(d3) : "r"(addr));
}

// ---------------- tensor-core GEMM, double-buffered smem, LDSM fragments -------
// Y = half((A@W)*norm), K=128. A fp32->fp16 or fp16; W split fp16 hi/lo.
// PDL: B tile 0 loads pre-sync; A (fresh agg output) loads post-sync.
template <int BN, typename AT>
__global__ __launch_bounds__(256) void gemm_tc_kernel(const AT* __restrict__ A,
                                                      const __half* __restrict__ Wh,
                                                      const __half* __restrict__ Wl,
                                                      __half* __restrict__ Yh) {
    constexpr int BM = 128, BK = 32, K = 128;
    constexpr int WN = BN / 4;   // 32 or 16
    constexpr int NT = WN / 8;   // 4 or 2
    constexpr int NJ = NT / 2;   // ldmatrix.x4 groups per B operand: 2 or 1
    constexpr int SA = 40;
    constexpr int ASZ = BM * SA;       // per-buffer A halves
    constexpr int BSZ = BN * SA;       // per-buffer B halves
    extern __shared__ __half smem[];
    __half* sA  = smem;                // 2 * ASZ
    __half* sBh = smem + 2 * ASZ;      // 2 * BSZ
    __half* sBl = sBh + 2 * BSZ;       // 2 * BSZ

    const int tid = threadIdx.x, lane = tid & 31, wid = tid >> 5;
    const int g = lane >> 2, t = lane & 3;
    const int mat = lane >> 3, mr = lane & 7;   // ldmatrix role
    const int wm = (wid & 1) * 64, wn = (wid >> 1) * WN;
    const int m0 = blockIdx.x * BM;

    const unsigned sA_u  = (unsigned)__cvta_generic_to_shared(sA);
    const unsigned sBh_u = (unsigned)__cvta_generic_to_shared(sBh);
    const unsigned sBl_u = (unsigned)__cvta_generic_to_shared(sBl);

    // ldmatrix relative half-offsets (within one buffer)
    unsigned aRel[4];
#pragma unroll
    for (int mt = 0; mt < 4; mt++)
        aRel[mt] = (unsigned)((wm + mt * 16 + (mat & 1) * 8 + mr) * SA + (mat >> 1) * 8);
    unsigned bRel[NJ];
#pragma unroll
    for (int j = 0; j < NJ; j++)
        bRel[j] = (unsigned)((wn + (j * 2 + (mat >> 1)) * 8 + mr) * SA + (mat & 1) * 8);

    float acc[4][NT][4];
#pragma unroll
    for (int i = 0; i < 4; i++)
#pragma unroll
        for (int j = 0; j < NT; j++)
#pragma unroll
            for (int q = 0; q < 4; q++) acc[i][j][q] = 0.f;

    float4 vaf[4];
    uint2  vah[4];
    uint4 vbh[2], vbl[2];

    auto loadA = [&](int k0) {
#pragma unroll
        for (int l = 0; l < 4; l++) {
            int idx = tid + l * 256, r = idx >> 3, c = idx & 7;
            if constexpr (sizeof(AT) == 4) {
                vaf[l] = make_float4(0.f, 0.f, 0.f, 0.f);
                if (m0 + r < NN)
                    vaf[l] = *(const float4*)((const float*)A + (size_t)(m0 + r) * K + k0 + c * 4);
            } else {
                vah[l] = make_uint2(0u, 0u);
                if (m0 + r < NN)
                    vah[l] = *(const uint2*)((const __half*)A + (size_t)(m0 + r) * K + k0 + c * 4);
            }
        }
    };
    auto loadB = [&](int k0) {
        if constexpr (BN == 128) {
            int n = tid >> 1, kh = (tid & 1) * 16;
            vbh[0] = *(const uint4*)&Wh[(size_t)n * K + k0 + kh];
            vbh[1] = *(const uint4*)&Wh[(size_t)n * K + k0 + kh + 8];
            vbl[0] = *(const uint4*)&Wl[(size_t)n * K + k0 + kh];
            vbl[1] = *(const uint4*)&Wl[(size_t)n * K + k0 + kh + 8];
        } else {
            int n = tid >> 2, kh = (tid & 3) * 8;
            vbh[0] = *(const uint4*)&Wh[(size_t)n * K + k0 + kh];
            vbl[0] = *(const uint4*)&Wl[(size_t)n * K + k0 + kh];
        }
    };
    auto storeTiles = [&](int buf) {
        __half* dA  = sA  + buf * ASZ;
        __half* dBh = sBh + buf * BSZ;
        __half* dBl = sBl + buf * BSZ;
#pragma unroll
        for (int l = 0; l < 4; l++) {
            int idx = tid + l * 256, r = idx >> 3, c = idx & 7;
            if constexpr (sizeof(AT) == 4) {
                float4 v = vaf[l];
                __half2 h01 = __floats2half2_rn(v.x, v.y);
                __half2 h23 = __floats2half2_rn(v.z, v.w);
                *(__half2*)&dA[r * SA + c * 4]     = h01;
                *(__half2*)&dA[r * SA + c * 4 + 2] = h23;
            } else {
                *(uint2*)&dA[r * SA + c * 4] = vah[l];
            }
        }
        if constexpr (BN == 128) {
            int n = tid >> 1, kh = (tid & 1) * 16;
            *(uint4*)&dBh[n * SA + kh]     = vbh[0];
            *(uint4*)&dBh[n * SA + kh + 8] = vbh[1];
            *(uint4*)&dBl[n * SA + kh]     = vbl[0];
            *(uint4*)&dBl[n * SA + kh + 8] = vbl[1];
        } else {
            int n = tid >> 2, kh = (tid & 3) * 8;
            *(uint4*)&dBh[n * SA + kh] = vbh[0];
            *(uint4*)&dBl[n * SA + kh] = vbl[0];
        }
    };

    loadB(0);                         // independent prologue (weights)
    cudaGridDependencySynchronize();  // wait for A producer
    loadA(0);
    storeTiles(0);
    __syncthreads();
#pragma unroll
    for (int s = 0; s < 4; s++) {
        if (s < 3) { loadA((s + 1) * BK); loadB((s + 1) * BK); }
        const int buf = s & 1;
        const unsigned cA_u  = sA_u  + (unsigned)(buf * ASZ) * 2u;
        const unsigned cBh_u = sBh_u + (unsigned)(buf * BSZ) * 2u;
        const unsigned cBl_u = sBl_u + (unsigned)(buf * BSZ) * 2u;
#pragma unroll
        for (int kk = 0; kk < BK; kk += 16) {
            unsigned bh[NT][2], bl[NT][2];
#pragma unroll
            for (int j = 0; j < NJ; j++) {
                unsigned off = (bRel[j] + (unsigned)kk) * 2u;
                ldsm_x4(bh[j * 2][0], bh[j * 2][1], bh[j * 2 + 1][0], bh[j * 2 + 1][1],
                        cBh_u + off);
                ldsm_x4(bl[j * 2][0], bl[j * 2][1], bl[j * 2 + 1][0], bl[j * 2 + 1][1],
                        cBl_u + off);
            }
#pragma unroll
            for (int mt = 0; mt < 4; mt++) {
                unsigned a0, a1, a2, a3;
                ldsm_x4(a0, a1, a2, a3, cA_u + (aRel[mt] + (unsigned)kk) * 2u);
#pragma unroll
                for (int nt = 0; nt < NT; nt++) {
                    mma_f16(acc[mt][nt], a0, a1, a2, a3, bh[nt][0], bh[nt][1]);
                    mma_f16(acc[mt][nt], a0, a1, a2, a3, bl[nt][0], bl[nt][1]);
                }
            }
        }
        if (s < 3) {
            storeTiles(1 - buf);
            __syncthreads();
        }
    }

#pragma unroll
    for (int mt = 0; mt < 4; mt++) {
        int r0 = m0 + wm + mt * 16 + g, r1 = r0 + 8;
        float n0 = (r0 < NN) ? g_norm[r0] : 0.f;
        float n1 = (r1 < NN) ? g_norm[r1] : 0.f;
#pragma unroll
        for (int nt = 0; nt < NT; nt++) {
            int col = wn + nt * 8 + 2 * t;
            if (r0 < NN) {
                __half2 h = __floats2half2_rn(acc[mt][nt][0] * n0, acc[mt][nt][1] * n0);
                *(__half2*)(Yh + (size_t)r0 * BN + col) = h;
            }
            if (r1 < NN) {
                __half2 h = __floats2half2_rn(acc[mt][nt][2] * n1, acc[mt][nt][3] * n1);
                *(__half2*)(Yh + (size_t)r1 * BN + col) = h;
            }
        }
    }
    cudaTriggerProgrammaticLaunchCompletion();
}

// ---------------- Aggregation: one warp per node, unroll-8 uint2 gather ---------
// PDL: rowptr/norm/bias pre-sync; Yh gathers (fresh GEMM output) post-sync.
// MODE 0: leaky(o) -> half buffer   MODE 1: x=(x+leaky(o))/2 fp16 in place
// MODE 3: MODE 1 + unrounded fp32 mirror to out2
template <int MODE>
__global__ __launch_bounds__(128) void agg_kernel(const __half* __restrict__ Yh,
                                                  const float* __restrict__ bias,
                                                  __half* __restrict__ xbuf,
                                                  float* __restrict__ out2) {
    int gw = (blockIdx.x * 128 + threadIdx.x) >> 5;
    int lane = threadIdx.x & 31;
    int beg = 0, end = 0;
    float nm = 0.f;
    float4 b = make_float4(0.f, 0.f, 0.f, 0.f);
    const int* __restrict__ col = g_col;
    int s0p = 0;
    if (gw < NN) {
        beg = g_rowptr[gw];
        end = g_rowptr[gw + 1];
        nm = g_norm[gw];
        b = ((const float4*)bias)[lane];
        if (beg < end) s0p = col[beg];   // prefetch first index pre-sync
    }
    cudaGridDependencySynchronize();
    if (gw >= NN) return;
    (void)s0p;
    const uint2* Y4 = (const uint2*)Yh;
    uint2 sv = Y4[(size_t)gw * 32 + lane];
    float2 f0 = u2f2(sv.x), f1 = u2f2(sv.y);
    float4 acc = make_float4(f0.x, f0.y, f1.x, f1.y);
    int e = beg;
#define ACCV(vv) { float2 p_ = u2f2(vv.x), q_ = u2f2(vv.y); \
                   acc.x += p_.x; acc.y += p_.y; acc.z += q_.x; acc.w += q_.y; }
    for (; e + 7 < end; e += 8) {
        int c0 = col[e],     c1 = col[e + 1], c2 = col[e + 2], c3 = col[e + 3];
        int c4 = col[e + 4], c5 = col[e + 5], c6 = col[e + 6], c7 = col[e + 7];
        uint2 v0 = Y4[(size_t)c0 * 32 + lane];
        uint2 v1 = Y4[(size_t)c1 * 32 + lane];
        uint2 v2 = Y4[(size_t)c2 * 32 + lane];
        uint2 v3 = Y4[(size_t)c3 * 32 + lane];
        uint2 v4 = Y4[(size_t)c4 * 32 + lane];
        uint2 v5 = Y4[(size_t)c5 * 32 + lane];
        uint2 v6 = Y4[(size_t)c6 * 32 + lane];
        uint2 v7 = Y4[(size_t)c7 * 32 + lane];
        ACCV(v0) ACCV(v1) ACCV(v2) ACCV(v3)
        ACCV(v4) ACCV(v5) ACCV(v6) ACCV(v7)
    }
    for (; e + 1 < end; e += 2) {
        int c0 = col[e], c1 = col[e + 1];
        uint2 v0 = Y4[(size_t)c0 * 32 + lane];
        uint2 v1 = Y4[(size_t)c1 * 32 + lane];
        ACCV(v0) ACCV(v1)
    }
    if (e < end) {
        uint2 v = Y4[(size_t)col[e] * 32 + lane];
        ACCV(v)
    }
#undef ACCV
    float4 o = make_float4(acc.x * nm + b.x, acc.y * nm + b.y,
                           acc.z * nm + b.z, acc.w * nm + b.w);
    size_t idx = (size_t)gw * 32 + lane;
    float4 l4 = make_float4(lk(o.x), lk(o.y), lk(o.z), lk(o.w));
    float4 nv;
    if constexpr (MODE == 0) {
        nv = l4;
    } else {
        uint2 xr = ((const uint2*)xbuf)[idx];
        float2 x0 = u2f2(xr.x), x1 = u2f2(xr.y);
        nv = make_float4((x0.x + l4.x) * 0.5f, (x0.y + l4.y) * 0.5f,
                         (x1.x + l4.z) * 0.5f, (x1.y + l4.w) * 0.5f);
        if constexpr (MODE == 3) ((float4*)out2)[idx] = nv;
    }
    uint2 p;
    __half2 h01 = __floats2half2_rn(nv.x, nv.y);
    __half2 h23 = __floats2half2_rn(nv.z, nv.w);
    p.x = *reinterpret_cast<unsigned*>(&h01);
    p.y = *reinterpret_cast<unsigned*>(&h23);
    ((uint2*)xbuf)[idx] = p;
    cudaTriggerProgrammaticLaunchCompletion();
}

// ---------------- final aggregation (output conv, D=64, no activation) --------
__global__ __launch_bounds__(128) void agg64_kernel(const __half* __restrict__ Yh,
                                                    const float* __restrict__ bias,
                                                    float* __restrict__ outp) {
    int gw = (blockIdx.x * 128 + threadIdx.x) >> 5;
    int lane = threadIdx.x & 31;
    int beg = 0, end = 0;
    float nm = 0.f;
    float2 b = make_float2(0.f, 0.f);
    const int* __restrict__ col = g_col;
    if (gw < NN) {
        beg = g_rowptr[gw];
        end = g_rowptr[gw + 1];
        nm = g_norm[gw];
        b = ((const float2*)bias)[lane];
    }
    cudaGridDependencySynchronize();
    if (gw >= NN) return;
    const unsigned* Y2 = (const unsigned*)Yh;
    float2 acc = u2f2(Y2[(size_t)gw * 32 + lane]);
    int e = beg;
    for (; e + 7 < end; e += 8) {
        int s0 = col[e],     s1 = col[e + 1], s2 = col[e + 2], s3 = col[e + 3];
        int s4 = col[e + 4], s5 = col[e + 5], s6 = col[e + 6], s7 = col[e + 7];
        float2 v0 = u2f2(Y2[(size_t)s0 * 32 + lane]);
        float2 v1 = u2f2(Y2[(size_t)s1 * 32 + lane]);
        float2 v2 = u2f2(Y2[(size_t)s2 * 32 + lane]);
        float2 v3 = u2f2(Y2[(size_t)s3 * 32 + lane]);
        float2 v4 = u2f2(Y2[(size_t)s4 * 32 + lane]);
        float2 v5 = u2f2(Y2[(size_t)s5 * 32 + lane]);
        float2 v6 = u2f2(Y2[(size_t)s6 * 32 + lane]);
        float2 v7 = u2f2(Y2[(size_t)s7 * 32 + lane]);
        acc.x += ((v0.x + v1.x) + (v2.x + v3.x)) + ((v4.x + v5.x) + (v6.x + v7.x));
        acc.y += ((v0.y + v1.y) + (v2.y + v3.y)) + ((v4.y + v5.y) + (v6.y + v7.y));
    }
    for (; e < end; e++) {
        float2 v = u2f2(Y2[(size_t)col[e] * 32 + lane]);
        acc.x += v.x; acc.y += v.y;
    }
    ((float2*)outp)[(size_t)gw * 32 + lane] =
        make_float2(acc.x * nm + b.x, acc.y * nm + b.y);
}

// ---------------- PDL launch helper ----------------
template <typename F, typename... Args>
static void pdl_launch(F* f, int grid, int block, size_t smem, Args... args) {
    cudaLaunchConfig_t cfg = {};
    cudaLaunchAttribute at[1];
    at[0].id = cudaLaunchAttributeProgrammaticStreamSerialization;
    at[0].val.programmaticStreamSerializationAllowed = 1;
    cfg.gridDim = dim3(grid, 1, 1);
    cfg.blockDim = dim3(block, 1, 1);
    cfg.dynamicSmemBytes = smem;
    cfg.stream = 0;
    cfg.attrs = at;
    cfg.numAttrs = 1;
    cudaLaunchKernelEx(&cfg, f, args...);
}

// ---------------- launch ----------------
extern "C" void kernel_launch(void* const* d_in, const int* in_sizes, int n_in,
                              void* d_out, int out_size) {
    const float* inputs = (const float*)d_in[0];
    const int*   edges  = (const int*)d_in[1];
    const float* b_in   = (const float*)d_in[3];
    const float* b1     = (const float*)d_in[5];
    const float* b2     = (const float*)d_in[7];
    const float* b_out  = (const float*)d_in[9];
    float* out = (float*)d_out;

    const int* src = edges;
    const int* dst = edges + NE;

    void *pyh, *phh, *pxh, *pwh, *pwl;
    cudaGetSymbolAddress(&pyh, g_yh);
    cudaGetSymbolAddress(&phh, g_hh);
    cudaGetSymbolAddress(&pxh, g_xh);
    cudaGetSymbolAddress(&pwh, g_wh);
    cudaGetSymbolAddress(&pwl, g_wl);
    __half* yh = (__half*)pyh;
    __half* hh = (__half*)phh;
    __half* xh = (__half*)pxh;
    __half* wh = (__half*)pwh;
    __half* wl = (__half*)pwl;

    // dynamic smem: 2 buffers of (A 128*40 + Bh BN*40 + Bl BN*40) halves
    const int SM128 = 2 * (128 * 40 + 2 * 128 * 40) * 2;  // 61440 B
    const int SM64  = 2 * (128 * 40 + 2 * 64 * 40) * 2;   // 40960 B
    cudaFuncSetAttribute(gemm_tc_kernel<128, float>,
                         cudaFuncAttributeMaxDynamicSharedMemorySize, SM128);
    cudaFuncSetAttribute(gemm_tc_kernel<128, __half>,
                         cudaFuncAttributeMaxDynamicSharedMemorySize, SM128);
    cudaFuncSetAttribute(gemm_tc_kernel<64, __half>,
                         cudaFuncAttributeMaxDynamicSharedMemorySize, SM64);

    const int GE = (NE + 255) / 256;
    const int GG = (NN + 127) / 128;       // gemm blocks
    const int GA = (NN * 32 + 127) / 128;  // agg blocks (warp/node)
    const int GW = (NMAT * HD * HD + 255) / 256;
    const size_t WSTEP = (size_t)HD * HD;

    // weight split/transpose (+ fused g_cnt zeroing) + CSR build
    pdl_launch(prep_w_kernel, GW, 256, 0,
               (const float*)d_in[2], (const float*)d_in[4],
               (const float*)d_in[6], (const float*)d_in[8]);
    pdl_launch(count_kernel, GE, 256, 0, dst);
    pdl_launch(scan_blocks_kernel, NSB, 1024, 0);
    pdl_launch(scan_fix_kernel, NSB, 1024, 0);
    pdl_launch(fill_kernel, GE, 256, 0, src, dst);

    // input conv
    pdl_launch(gemm_tc_kernel<128, float>, GG, 256, SM128,
               inputs, (const __half*)wh, (const __half*)wl, yh);
    pdl_launch(agg_kernel<0>, GA, 128, 0,
               (const __half*)yh, b_in, xh, (float*)nullptr);

    // 6 residual blocks; last one mirrors fp32 x into d_out's second half
    for (int i = 0; i < 6; i++) {
        pdl_launch(gemm_tc_kernel<128, __half>, GG, 256, SM128,
                   (const __half*)xh, (const __half*)(wh + (size_t)(1 + i) * WSTEP),
                   (const __half*)(wl + (size_t)(1 + i) * WSTEP), yh);
        pdl_launch(agg_kernel<0>, GA, 128, 0,
                   (const __half*)yh, b1 + (size_t)i * HD, hh, (float*)nullptr);
        pdl_launch(gemm_tc_kernel<128, __half>, GG, 256, SM128,
                   (const __half*)hh, (const __half*)(wh + (size_t)(7 + i) * WSTEP),
                   (const __half*)(wl + (size_t)(7 + i) * WSTEP), yh);
        if (i < 5)
            pdl_launch(agg_kernel<1>, GA, 128, 0,
                       (const __half*)yh, b2 + (size_t)i * HD, xh, (float*)nullptr);
        else
            pdl_launch(agg_kernel<3>, GA, 128, 0,
                       (const __half*)yh, b2 + (size_t)i * HD, xh,
                       out + (size_t)NN * 64);
    }

    // output conv (no activation), writes first N*64 floats of d_out
    pdl_launch(gemm_tc_kernel<64, __half>, GG, 256, SM64,
               (const __half*)xh, (const __half*)(wh + (size_t)13 * WSTEP),
               (const __half*)(wl + (size_t)13 * WSTEP), yh);
    pdl_launch(agg64_kernel, GA, 128, 0,
               (const __half*)yh, b_out, out);
}

// round 17
// speedup vs baseline: 1.4329x; 1.1849x over previous
#include <cuda_runtime.h>
#include <cuda_fp16.h>
#include <cuda_bf16.h>

#define NN 50000
#define NE 800000
#define HD 128
#define NMAT 14
#define NSB 49   // scan blocks: ceil(50000/1024)

// ---------------- device scratch (no allocations allowed) ----------------
__device__ __half  g_yh[(size_t)NN * HD];   // fp16 messages (GEMM output, norm-scaled)
__device__ __half  g_hh[(size_t)NN * HD];   // fp16 block intermediate h
__device__ __half  g_xh[(size_t)NN * HD];   // fp16 running x master
__device__ float   g_norm[NN];
__device__ int     g_rowptr[NN + 1];
__device__ int     g_cnt[NN];
__device__ int     g_off[NN];
__device__ int     g_col[NE];
__device__ int     g_bsum[NSB];             // raw per-block totals
__device__ __half  g_wh[(size_t)NMAT * HD * HD];  // weights, n-major, fp16

__device__ __forceinline__ float lk(float v) { return v >= 0.f ? v : 0.01f * v; }

__device__ __forceinline__ float2 u2f2(unsigned u) {
    __half2 h = *reinterpret_cast<__half2*>(&u);
    return __half22float2(h);
}

// ---------------- CSR build ----------------
__global__ void count_kernel(const int* __restrict__ dst) {
    int e = blockIdx.x * blockDim.x + threadIdx.x;
    int d = (e < NE) ? dst[e] : 0;          // harness input: safe pre-sync
    cudaGridDependencySynchronize();        // wait for g_cnt zeroing (in prep_w)
    cudaTriggerProgrammaticLaunchCompletion();
    if (e < NE) atomicAdd(&g_cnt[d], 1);
}

__global__ __launch_bounds__(1024) void scan_blocks_kernel() {
    __shared__ int ws[32];
    int tid = threadIdx.x, lane = tid & 31, wid = tid >> 5;
    int i = blockIdx.x * 1024 + tid;
    cudaGridDependencySynchronize();        // g_cnt dependent
    int v = (i < NN) ? g_cnt[i] : 0;
    int x = v;
#pragma unroll
    for (int d = 1; d < 32; d <<= 1) {
        int t = __shfl_up_sync(0xffffffffu, x, d);
        if (lane >= d) x += t;
    }
    if (lane == 31) ws[wid] = x;
    __syncthreads();
    if (wid == 0) {
        int s = ws[lane];
#pragma unroll
        for (int d = 1; d < 32; d <<= 1) {
            int t = __shfl_up_sync(0xffffffffu, s, d);
            if (lane >= d) s += t;
        }
        ws[lane] = s;
    }
    __syncthreads();
    int off = wid ? ws[wid - 1] : 0;
    if (i < NN) g_rowptr[i] = off + x - v;
    if (tid == 1023) g_bsum[blockIdx.x] = off + x;
    cudaTriggerProgrammaticLaunchCompletion();
}

__global__ __launch_bounds__(1024) void scan_fix_kernel() {
    __shared__ int s_off;
    int tid = threadIdx.x;
    cudaGridDependencySynchronize();        // rowptr/bsum dependent
    if (tid < 32) {
        int b = blockIdx.x;
        int t0 = (tid < NSB && tid < b) ? g_bsum[tid] : 0;
        int t1 = (tid + 32 < NSB && tid + 32 < b) ? g_bsum[tid + 32] : 0;
        int s = t0 + t1;
#pragma unroll
        for (int d = 16; d >= 1; d >>= 1) s += __shfl_xor_sync(0xffffffffu, s, d);
        if (tid == 0) s_off = s;
    }
    __syncthreads();
    int i = blockIdx.x * 1024 + tid;
    if (i < NN) {
        int r = g_rowptr[i] + s_off;
        g_rowptr[i] = r;
        g_off[i] = r;
        g_norm[i] = rsqrtf(1.0f + (float)g_cnt[i]);
    }
    if (blockIdx.x == 0 && tid == 0) g_rowptr[NN] = NE;
    cudaTriggerProgrammaticLaunchCompletion();
}

__global__ void fill_kernel(const int* __restrict__ src, const int* __restrict__ dst) {
    int e = blockIdx.x * blockDim.x + threadIdx.x;
    int s = 0, d = 0;
    if (e < NE) { s = src[e]; d = dst[e]; }  // harness inputs: safe pre-sync
    cudaGridDependencySynchronize();         // g_off dependent
    if (e < NE) {
        int p = atomicAdd(&g_off[d], 1);
        g_col[p] = s;
    }
    cudaTriggerProgrammaticLaunchCompletion();
}

// ---------------- weight prep + g_cnt zeroing ----------------
__global__ void prep_w_kernel(const float* __restrict__ w_in, const float* __restrict__ w1,
                              const float* __restrict__ w2, const float* __restrict__ w_out) {
    int idx = blockIdx.x * blockDim.x + threadIdx.x;
    if (idx >= NMAT * HD * HD) return;
    int mat = idx >> 14;
    int rem = idx & 16383;
    int n = rem >> 7, k = rem & 127;
    float v;
    if (mat == 0)       v = w_in[k * HD + n];
    else if (mat <= 6)  v = w1[(size_t)(mat - 1) * HD * HD + k * HD + n];
    else if (mat <= 12) v = w2[(size_t)(mat - 7) * HD * HD + k * HD + n];
    else                v = (n < 64) ? w_out[k * 64 + n] : 0.f;
    cudaGridDependencySynchronize();   // guard vs prior graph replay's readers
    if (idx < NN) g_cnt[idx] = 0;      // fused zeroing (replaces memset launch)
    g_wh[idx] = __float2half_rn(v);
    cudaTriggerProgrammaticLaunchCompletion();
}

// ---------------- fp16 MMA helper (fp32 accumulate) ----------------
__device__ __forceinline__ void mma_f16(float* c, unsigned a0, unsigned a1, unsigned a2,
                                        unsigned a3, unsigned b0, unsigned b1) {
    asm volatile(
        "mma.sync.aligned.m16n8k16.row.col.f32.f16.f16.f32 "
        "{%0,%1,%2,%3}, {%4,%5,%6,%7}, {%8,%9}, {%0,%1,%2,%3};"
        : "+f"(c[0]), "+f"(c[1]), "+f"(c[2]), "+f"(c[3])
        : "r"(a0), "r"(a1), "r"(a2), "r"(a3), "r"(b0), "r"(b1));
}

__device__ __forceinline__ void ldsm_x4(unsigned& d0, unsigned& d1, unsigned& d2,
                                        unsigned& d3, unsigned addr) {
    asm volatile("ldmatrix.sync.aligned.m8n8.x4.shared.b16 {%0,%1,%2,%3}, [%4];"
                 : "=r"(d0), "=r"(d1), "=r"(d2), "=r"(d3) : "r"(addr));
}

// ---------------- tensor-core GEMM, double-buffered smem, LDSM fragments -------
// Y = half((A@W)*norm), K=128. A fp32->fp16 or fp16; W single fp16.
// PDL: B tile 0 loads pre-sync; A (fresh agg output) loads post-sync.
template <int BN, typename AT>
__global__ __launch_bounds__(256) void gemm_tc_kernel(const AT* __restrict__ A,
                                                      const __half* __restrict__ Wh,
                                                      __half* __restrict__ Yh) {
    constexpr int BM = 128, BK = 32, K = 128;
    constexpr int WN = BN / 4;   // 32 or 16
    constexpr int NT = WN / 8;   // 4 or 2
    constexpr int NJ = NT / 2;   // ldmatrix.x4 groups per B operand: 2 or 1
    constexpr int SA = 40;
    constexpr int ASZ = BM * SA;       // per-buffer A halves
    constexpr int BSZ = BN * SA;       // per-buffer B halves
    extern __shared__ __half smem[];
    __half* sA  = smem;                // 2 * ASZ
    __half* sBh = smem + 2 * ASZ;      // 2 * BSZ

    const int tid = threadIdx.x, lane = tid & 31, wid = tid >> 5;
    const int g = lane >> 2, t = lane & 3;
    const int mat = lane >> 3, mr = lane & 7;   // ldmatrix role
    const int wm = (wid & 1) * 64, wn = (wid >> 1) * WN;
    const int m0 = blockIdx.x * BM;

    const unsigned sA_u  = (unsigned)__cvta_generic_to_shared(sA);
    const unsigned sBh_u = (unsigned)__cvta_generic_to_shared(sBh);

    // ldmatrix relative half-offsets (within one buffer)
    unsigned aRel[4];
#pragma unroll
    for (int mt = 0; mt < 4; mt++)
        aRel[mt] = (unsigned)((wm + mt * 16 + (mat & 1) * 8 + mr) * SA + (mat >> 1) * 8);
    unsigned bRel[NJ];
#pragma unroll
    for (int j = 0; j < NJ; j++)
        bRel[j] = (unsigned)((wn + (j * 2 + (mat >> 1)) * 8 + mr) * SA + (mat & 1) * 8);

    float acc[4][NT][4];
#pragma unroll
    for (int i = 0; i < 4; i++)
#pragma unroll
        for (int j = 0; j < NT; j++)
#pragma unroll
            for (int q = 0; q < 4; q++) acc[i][j][q] = 0.f;

    float4 vaf[4];
    uint2  vah[4];
    uint4 vbh[2];

    auto loadA = [&](int k0) {
#pragma unroll
        for (int l = 0; l < 4; l++) {
            int idx = tid + l * 256, r = idx >> 3, c = idx & 7;
            if constexpr (sizeof(AT) == 4) {
                vaf[l] = make_float4(0.f, 0.f, 0.f, 0.f);
                if (m0 + r < NN)
                    vaf[l] = *(const float4*)((const float*)A + (size_t)(m0 + r) * K + k0 + c * 4);
            } else {
                vah[l] = make_uint2(0u, 0u);
                if (m0 + r < NN)
                    vah[l] = *(const uint2*)((const __half*)A + (size_t)(m0 + r) * K + k0 + c * 4);
            }
        }
    };
    auto loadB = [&](int k0) {
        if constexpr (BN == 128) {
            int n = tid >> 1, kh = (tid & 1) * 16;
            vbh[0] = *(const uint4*)&Wh[(size_t)n * K + k0 + kh];
            vbh[1] = *(const uint4*)&Wh[(size_t)n * K + k0 + kh + 8];
        } else {
            int n = tid >> 2, kh = (tid & 3) * 8;
            vbh[0] = *(const uint4*)&Wh[(size_t)n * K + k0 + kh];
        }
    };
    auto storeTiles = [&](int buf) {
        __half* dA  = sA  + buf * ASZ;
        __half* dBh = sBh + buf * BSZ;
#pragma unroll
        for (int l = 0; l < 4; l++) {
            int idx = tid + l * 256, r = idx >> 3, c = idx & 7;
            if constexpr (sizeof(AT) == 4) {
                float4 v = vaf[l];
                __half2 h01 = __floats2half2_rn(v.x, v.y);
                __half2 h23 = __floats2half2_rn(v.z, v.w);
                *(__half2*)&dA[r * SA + c * 4]     = h01;
                *(__half2*)&dA[r * SA + c * 4 + 2] = h23;
            } else {
                *(uint2*)&dA[r * SA + c * 4] = vah[l];
            }
        }
        if constexpr (BN == 128) {
            int n = tid >> 1, kh = (tid & 1) * 16;
            *(uint4*)&dBh[n * SA + kh]     = vbh[0];
            *(uint4*)&dBh[n * SA + kh + 8] = vbh[1];
        } else {
            int n = tid >> 2, kh = (tid & 3) * 8;
            *(uint4*)&dBh[n * SA + kh] = vbh[0];
        }
    };

    loadB(0);                         // independent prologue (weights)
    cudaGridDependencySynchronize();  // wait for A producer
    loadA(0);
    storeTiles(0);
    __syncthreads();
#pragma unroll
    for (int s = 0; s < 4; s++) {
        if (s < 3) { loadA((s + 1) * BK); loadB((s + 1) * BK); }
        const int buf = s & 1;
        const unsigned cA_u  = sA_u  + (unsigned)(buf * ASZ) * 2u;
        const unsigned cBh_u = sBh_u + (unsigned)(buf * BSZ) * 2u;
#pragma unroll
        for (int kk = 0; kk < BK; kk += 16) {
            unsigned bh[NT][2];
#pragma unroll
            for (int j = 0; j < NJ; j++) {
                unsigned off = (bRel[j] + (unsigned)kk) * 2u;
                ldsm_x4(bh[j * 2][0], bh[j * 2][1], bh[j * 2 + 1][0], bh[j * 2 + 1][1],
                        cBh_u + off);
            }
#pragma unroll
            for (int mt = 0; mt < 4; mt++) {
                unsigned a0, a1, a2, a3;
                ldsm_x4(a0, a1, a2, a3, cA_u + (aRel[mt] + (unsigned)kk) * 2u);
#pragma unroll
                for (int nt = 0; nt < NT; nt++) {
                    mma_f16(acc[mt][nt], a0, a1, a2, a3, bh[nt][0], bh[nt][1]);
                }
            }
        }
        if (s < 3) {
            storeTiles(1 - buf);
            __syncthreads();
        }
    }

#pragma unroll
    for (int mt = 0; mt < 4; mt++) {
        int r0 = m0 + wm + mt * 16 + g, r1 = r0 + 8;
        float n0 = (r0 < NN) ? g_norm[r0] : 0.f;
        float n1 = (r1 < NN) ? g_norm[r1] : 0.f;
#pragma unroll
        for (int nt = 0; nt < NT; nt++) {
            int col = wn + nt * 8 + 2 * t;
            if (r0 < NN) {
                __half2 h = __floats2half2_rn(acc[mt][nt][0] * n0, acc[mt][nt][1] * n0);
                *(__half2*)(Yh + (size_t)r0 * BN + col) = h;
            }
            if (r1 < NN) {
                __half2 h = __floats2half2_rn(acc[mt][nt][2] * n1, acc[mt][nt][3] * n1);
                *(__half2*)(Yh + (size_t)r1 * BN + col) = h;
            }
        }
    }
    cudaTriggerProgrammaticLaunchCompletion();
}

// ---------------- Aggregation: one warp per node, unroll-8 uint2 gather ---------
// PDL: rowptr/norm/bias pre-sync; Yh gathers (fresh GEMM output) post-sync.
// MODE 0: leaky(o) -> half buffer   MODE 1: x=(x+leaky(o))/2 fp16 in place
// MODE 3: MODE 1 + unrounded fp32 mirror to out2
template <int MODE>
__global__ __launch_bounds__(128) void agg_kernel(const __half* __restrict__ Yh,
                                                  const float* __restrict__ bias,
                                                  __half* __restrict__ xbuf,
                                                  float* __restrict__ out2) {
    int gw = (blockIdx.x * 128 + threadIdx.x) >> 5;
    int lane = threadIdx.x & 31;
    int beg = 0, end = 0;
    float nm = 0.f;
    float4 b = make_float4(0.f, 0.f, 0.f, 0.f);
    const int* __restrict__ col = g_col;
    int s0p = 0;
    if (gw < NN) {
        beg = g_rowptr[gw];
        end = g_rowptr[gw + 1];
        nm = g_norm[gw];
        b = ((const float4*)bias)[lane];
        if (beg < end) s0p = col[beg];   // prefetch first index pre-sync
    }
    cudaGridDependencySynchronize();
    if (gw >= NN) return;
    (void)s0p;
    const uint2* Y4 = (const uint2*)Yh;
    uint2 sv = Y4[(size_t)gw * 32 + lane];
    float2 f0 = u2f2(sv.x), f1 = u2f2(sv.y);
    float4 acc = make_float4(f0.x, f0.y, f1.x, f1.y);
    int e = beg;
#define ACCV(vv) { float2 p_ = u2f2(vv.x), q_ = u2f2(vv.y); \
                   acc.x += p_.x; acc.y += p_.y; acc.z += q_.x; acc.w += q_.y; }
    for (; e + 7 < end; e += 8) {
        int c0 = col[e],     c1 = col[e + 1], c2 = col[e + 2], c3 = col[e + 3];
        int c4 = col[e + 4], c5 = col[e + 5], c6 = col[e + 6], c7 = col[e + 7];
        uint2 v0 = Y4[(size_t)c0 * 32 + lane];
        uint2 v1 = Y4[(size_t)c1 * 32 + lane];
        uint2 v2 = Y4[(size_t)c2 * 32 + lane];
        uint2 v3 = Y4[(size_t)c3 * 32 + lane];
        uint2 v4 = Y4[(size_t)c4 * 32 + lane];
        uint2 v5 = Y4[(size_t)c5 * 32 + lane];
        uint2 v6 = Y4[(size_t)c6 * 32 + lane];
        uint2 v7 = Y4[(size_t)c7 * 32 + lane];
        ACCV(v0) ACCV(v1) ACCV(v2) ACCV(v3)
        ACCV(v4) ACCV(v5) ACCV(v6) ACCV(v7)
    }
    for (; e + 1 < end; e += 2) {
        int c0 = col[e], c1 = col[e + 1];
        uint2 v0 = Y4[(size_t)c0 * 32 + lane];
        uint2 v1 = Y4[(size_t)c1 * 32 + lane];
        ACCV(v0) ACCV(v1)
    }
    if (e < end) {
        uint2 v = Y4[(size_t)col[e] * 32 + lane];
        ACCV(v)
    }
#undef ACCV
    float4 o = make_float4(acc.x * nm + b.x, acc.y * nm + b.y,
                           acc.z * nm + b.z, acc.w * nm + b.w);
    size_t idx = (size_t)gw * 32 + lane;
    float4 l4 = make_float4(lk(o.x), lk(o.y), lk(o.z), lk(o.w));
    float4 nv;
    if constexpr (MODE == 0) {
        nv = l4;
    } else {
        uint2 xr = ((const uint2*)xbuf)[idx];
        float2 x0 = u2f2(xr.x), x1 = u2f2(xr.y);
        nv = make_float4((x0.x + l4.x) * 0.5f, (x0.y + l4.y) * 0.5f,
                         (x1.x + l4.z) * 0.5f, (x1.y + l4.w) * 0.5f);
        if constexpr (MODE == 3) ((float4*)out2)[idx] = nv;
    }
    uint2 p;
    __half2 h01 = __floats2half2_rn(nv.x, nv.y);
    __half2 h23 = __floats2half2_rn(nv.z, nv.w);
    p.x = *reinterpret_cast<unsigned*>(&h01);
    p.y = *reinterpret_cast<unsigned*>(&h23);
    ((uint2*)xbuf)[idx] = p;
    cudaTriggerProgrammaticLaunchCompletion();
}

// ---------------- final aggregation (output conv, D=64, no activation) --------
__global__ __launch_bounds__(128) void agg64_kernel(const __half* __restrict__ Yh,
                                                    const float* __restrict__ bias,
                                                    float* __restrict__ outp) {
    int gw = (blockIdx.x * 128 + threadIdx.x) >> 5;
    int lane = threadIdx.x & 31;
    int beg = 0, end = 0;
    float nm = 0.f;
    float2 b = make_float2(0.f, 0.f);
    const int* __restrict__ col = g_col;
    if (gw < NN) {
        beg = g_rowptr[gw];
        end = g_rowptr[gw + 1];
        nm = g_norm[gw];
        b = ((const float2*)bias)[lane];
    }
    cudaGridDependencySynchronize();
    if (gw >= NN) return;
    const unsigned* Y2 = (const unsigned*)Yh;
    float2 acc = u2f2(Y2[(size_t)gw * 32 + lane]);
    int e = beg;
    for (; e + 7 < end; e += 8) {
        int s0 = col[e],     s1 = col[e + 1], s2 = col[e + 2], s3 = col[e + 3];
        int s4 = col[e + 4], s5 = col[e + 5], s6 = col[e + 6], s7 = col[e + 7];
        float2 v0 = u2f2(Y2[(size_t)s0 * 32 + lane]);
        float2 v1 = u2f2(Y2[(size_t)s1 * 32 + lane]);
        float2 v2 = u2f2(Y2[(size_t)s2 * 32 + lane]);
        float2 v3 = u2f2(Y2[(size_t)s3 * 32 + lane]);
        float2 v4 = u2f2(Y2[(size_t)s4 * 32 + lane]);
        float2 v5 = u2f2(Y2[(size_t)s5 * 32 + lane]);
        float2 v6 = u2f2(Y2[(size_t)s6 * 32 + lane]);
        float2 v7 = u2f2(Y2[(size_t)s7 * 32 + lane]);
        acc.x += ((v0.x + v1.x) + (v2.x + v3.x)) + ((v4.x + v5.x) + (v6.x + v7.x));
        acc.y += ((v0.y + v1.y) + (v2.y + v3.y)) + ((v4.y + v5.y) + (v6.y + v7.y));
    }
    for (; e < end; e++) {
        float2 v = u2f2(Y2[(size_t)col[e] * 32 + lane]);
        acc.x += v.x; acc.y += v.y;
    }
    ((float2*)outp)[(size_t)gw * 32 + lane] =
        make_float2(acc.x * nm + b.x, acc.y * nm + b.y);
}

// ---------------- PDL launch helper ----------------
template <typename F, typename... Args>
static void pdl_launch(F* f, int grid, int block, size_t smem, Args... args) {
    cudaLaunchConfig_t cfg = {};
    cudaLaunchAttribute at[1];
    at[0].id = cudaLaunchAttributeProgrammaticStreamSerialization;
    at[0].val.programmaticStreamSerializationAllowed = 1;
    cfg.gridDim = dim3(grid, 1, 1);
    cfg.blockDim = dim3(block, 1, 1);
    cfg.dynamicSmemBytes = smem;
    cfg.stream = 0;
    cfg.attrs = at;
    cfg.numAttrs = 1;
    cudaLaunchKernelEx(&cfg, f, args...);
}

// ---------------- launch ----------------
extern "C" void kernel_launch(void* const* d_in, const int* in_sizes, int n_in,
                              void* d_out, int out_size) {
    const float* inputs = (const float*)d_in[0];
    const int*   edges  = (const int*)d_in[1];
    const float* b_in   = (const float*)d_in[3];
    const float* b1     = (const float*)d_in[5];
    const float* b2     = (const float*)d_in[7];
    const float* b_out  = (const float*)d_in[9];
    float* out = (float*)d_out;

    const int* src = edges;
    const int* dst = edges + NE;

    void *pyh, *phh, *pxh, *pwh;
    cudaGetSymbolAddress(&pyh, g_yh);
    cudaGetSymbolAddress(&phh, g_hh);
    cudaGetSymbolAddress(&pxh, g_xh);
    cudaGetSymbolAddress(&pwh, g_wh);
    __half* yh = (__half*)pyh;
    __half* hh = (__half*)phh;
    __half* xh = (__half*)pxh;
    __half* wh = (__half*)pwh;

    // dynamic smem: 2 buffers of (A 128*40 + Bh BN*40) halves
    const int SM128 = 2 * (128 * 40 + 128 * 40) * 2;  // 40960 B
    const int SM64  = 2 * (128 * 40 + 64 * 40) * 2;   // 30720 B
    cudaFuncSetAttribute(gemm_tc_kernel<128, float>,
                         cudaFuncAttributeMaxDynamicSharedMemorySize, SM128);
    cudaFuncSetAttribute(gemm_tc_kernel<128, __half>,
                         cudaFuncAttributeMaxDynamicSharedMemorySize, SM128);
    cudaFuncSetAttribute(gemm_tc_kernel<64, __half>,
                         cudaFuncAttributeMaxDynamicSharedMemorySize, SM64);

    const int GE = (NE + 255) / 256;
    const int GG = (NN + 127) / 128;       // gemm blocks
    const int GA = (NN * 32 + 127) / 128;  // agg blocks (warp/node)
    const int GW = (NMAT * HD * HD + 255) / 256;
    const size_t WSTEP = (size_t)HD * HD;

    // weight transpose (+ fused g_cnt zeroing) + CSR build
    pdl_launch(prep_w_kernel, GW, 256, 0,
               (const float*)d_in[2], (const float*)d_in[4],
               (const float*)d_in[6], (const float*)d_in[8]);
    pdl_launch(count_kernel, GE, 256, 0, dst);
    pdl_launch(scan_blocks_kernel, NSB, 1024, 0);
    pdl_launch(scan_fix_kernel, NSB, 1024, 0);
    pdl_launch(fill_kernel, GE, 256, 0, src, dst);

    // input conv
    pdl_launch(gemm_tc_kernel<128, float>, GG, 256, SM128,
               inputs, (const __half*)wh, yh);
    pdl_launch(agg_kernel<0>, GA, 128, 0,
               (const __half*)yh, b_in, xh, (float*)nullptr);

    // 6 residual blocks; last one mirrors fp32 x into d_out's second half
    for (int i = 0; i < 6; i++) {
        pdl_launch(gemm_tc_kernel<128, __half>, GG, 256, SM128,
                   (const __half*)xh, (const __half*)(wh + (size_t)(1 + i) * WSTEP), yh);
        pdl_launch(agg_kernel<0>, GA, 128, 0,
                   (const __half*)yh, b1 + (size_t)i * HD, hh, (float*)nullptr);
        pdl_launch(gemm_tc_kernel<128, __half>, GG, 256, SM128,
                   (const __half*)hh, (const __half*)(wh + (size_t)(7 + i) * WSTEP), yh);
        if (i < 5)
            pdl_launch(agg_kernel<1>, GA, 128, 0,
                       (const __half*)yh, b2 + (size_t)i * HD, xh, (float*)nullptr);
        else
            pdl_launch(agg_kernel<3>, GA, 128, 0,
                       (const __half*)yh, b2 + (size_t)i * HD, xh,
                       out + (size_t)NN * 64);
    }

    // output conv (no activation), writes first N*64 floats of d_out
    pdl_launch(gemm_tc_kernel<64, __half>, GG, 256, SM64,
               (const __half*)xh, (const __half*)(wh + (size_t)13 * WSTEP), yh);
    pdl_launch(agg64_kernel, GA, 128, 0,
               (const __half*)yh, b_out, out);
}